// round 13
// baseline (speedup 1.0000x reference)
#include <cuda_runtime.h>
#include <cuda_fp16.h>
#include <math.h>
#include <stdint.h>

// VectorQuantizerEMA: D=64, K=512, N=B*T=262144.
// fp16 HMMA screen (round-11 epilogue: per-chunk min + (m2,k1)) +
// per-row singleton shortcut (no rescore for ~95% of rows) +
// staged warp exact fp32 rescore for ambiguous rows. Single launch.
#define DIM 64
#define NCODES 512
#define TILE_M 128
#define TPB 256
#define MAXGRID 256
#define NCHUNK 32
#define CMIN_STRIDE 33
#define QCAP 4096
#define XSTRIDE 272
#define STG_STRIDE 4352

__device__ float g_part[MAXGRID];
__device__ unsigned int g_ticket;

// ---------- smem layout (bytes) ----------
#define OFF_AH     0                   // A fp16 [128 x 128B] SW128      (16384)
#define OFF_BH     16384               // B fp16 [512 x 128B] SW128      (65536)
#define OFF_X      81920               // x fp32 [128 x 272B]            (34816)
#define OFF_EEW    116736              // float4[512]: (ee, w, s, 0)     (8192)
#define OFF_CMIN   124928              // f32[128][33] chunk min         (16896)
#define OFF_CAUX   141824              // u32[128][33] fp16(m2)<<16|k1   (16896)
#define OFF_TROW   158720              // f32[128] row min               (512)
#define OFF_SXX    159232              // f32[128]                       (512)
#define OFF_BEST   159744              // u64[128]                       (1024)
#define OFF_QUEUE  160768              // u32[QCAP] chunk entries        (16384)
#define OFF_CNT    177152              // qn @+0, smax @+8               (16)
#define OFF_STAGE  177168              // 8 warps x 4352B                (34816)
#define OFF_RED    211984              // float[256]                     (1024)
#define SMEM_TOTAL 213008

#define SWZ(o) ((uint32_t)(o) ^ ((((uint32_t)(o)) >> 3) & 0x70))

typedef unsigned long long u64;

__device__ __forceinline__ uint32_t smem_u32(const void* p) {
    uint32_t a;
    asm("{ .reg .u64 t; cvta.to.shared.u64 t, %1; cvt.u32.u64 %0, t; }"
        : "=r"(a) : "l"(p));
    return a;
}
__device__ __forceinline__ void ldm4(uint32_t* r, uint32_t addr) {
    asm volatile("ldmatrix.sync.aligned.m8n8.x4.shared.b16 {%0,%1,%2,%3}, [%4];"
                 : "=r"(r[0]), "=r"(r[1]), "=r"(r[2]), "=r"(r[3]) : "r"(addr));
}
__device__ __forceinline__ void mma16816(float* c, const uint32_t* a,
                                         const uint32_t* b) {
    asm volatile(
        "mma.sync.aligned.m16n8k16.row.col.f32.f16.f16.f32 "
        "{%0,%1,%2,%3}, {%4,%5,%6,%7}, {%8,%9}, {%0,%1,%2,%3};"
        : "+f"(c[0]), "+f"(c[1]), "+f"(c[2]), "+f"(c[3])
        : "r"(a[0]), "r"(a[1]), "r"(a[2]), "r"(a[3]), "r"(b[0]), "r"(b[1]));
}
__device__ __forceinline__ uint32_t packh2(float a, float b) {
    __half2 h = __floats2half2_rn(a, b);
    return *(uint32_t*)&h;
}

__global__ void __launch_bounds__(TPB, 1)
vq_hmma(const float* __restrict__ inputs,
        const float* __restrict__ emb,
        const float* __restrict__ ema,
        float* __restrict__ out_q,
        float* __restrict__ out_idx,
        float* __restrict__ out_loss,
        int ntiles, float inv_count) {
    extern __shared__ char smem[];
    const uint32_t sbase = smem_u32(smem);
    const int tid  = threadIdx.x;
    const int wid  = tid >> 5;
    const int lane = tid & 31;

    float4* eew   = (float4*)(smem + OFF_EEW);
    float*  cmin  = (float*)(smem + OFF_CMIN);
    uint32_t* caux = (uint32_t*)(smem + OFF_CAUX);
    float*  trow  = (float*)(smem + OFF_TROW);
    float*  sxx   = (float*)(smem + OFF_SXX);
    u64*    best64 = (u64*)(smem + OFF_BEST);
    uint32_t* queue = (uint32_t*)(smem + OFF_QUEUE);
    int* qn = (int*)(smem + OFF_CNT);

    if (tid == 0) *(int*)(smem + OFF_CNT + 8) = 0;
    __syncthreads();

    // ---- codebook init: fp16 plane + (ee, w, s); ee = serial fma chain ----
    for (int k = tid; k < NCODES; k += TPB) {
        const float* e = emb + k * DIM;
        float ee = 0.f;
#pragma unroll
        for (int d = 0; d < DIM; d++) ee += e[d] * e[d];
        const float4* ep = (const float4*)e;
#pragma unroll
        for (int q = 0; q < 16; q++) {
            float4 e4 = ep[q];
            uint2 hv = make_uint2(packh2(e4.x, e4.y), packh2(e4.z, e4.w));
            *(uint2*)(smem + OFF_BH + SWZ(k * 128 + q * 8)) = hv;
        }
        float w = sqrtf(ema[k]);
        float s = sqrtf(ee) * w;
        eew[k] = make_float4(ee, w, s, 0.f);
        atomicMax((int*)(smem + OFF_CNT + 8), __float_as_int(s));  // s >= 0
    }
    __syncthreads();
    const float smax = *(float*)(smem + OFF_CNT + 8);

    // fragment geometry
    const int R0 = wid * 16;
    const int rowA = R0 + ((lane >> 3) & 1) * 8 + (lane & 7);
    const uint32_t kaddA = ((lane >> 4) & 1) * 16;
    const int rowB = ((lane >> 4) & 1) * 8 + (lane & 7);
    const uint32_t kaddB = ((lane >> 3) & 1) * 16;
    const int rrow0 = R0 + (lane >> 2);
    const int rrow1 = rrow0 + 8;
    const int jcol  = (lane & 3) * 2;

    float lsum = 0.f;

    for (int tile = blockIdx.x; tile < ntiles; tile += gridDim.x) {
        const size_t base = (size_t)tile * TILE_M;
        __syncthreads();  // prev tile fully consumed

        // ---- A-build: x -> smem fp32 (padded) + fp16 plane ----
        if (tid < TILE_M) {
            const float4* xp = (const float4*)(inputs + (base + tid) * DIM);
            float4* xs = (float4*)(smem + OFF_X + tid * XSTRIDE);
            float xxr = 0.f;
#pragma unroll
            for (int q = 0; q < 16; q++) {
                float4 v = xp[q];
                xs[q] = v;
                xxr += v.x * v.x + v.y * v.y + v.z * v.z + v.w * v.w;
                uint2 hv = make_uint2(packh2(v.x, v.y), packh2(v.z, v.w));
                *(uint2*)(smem + OFF_AH + SWZ(tid * 128 + q * 8)) = hv;
            }
            sxx[tid] = xxr;
        }
        if (tid == 0) *qn = 0;
        __syncthreads();  // A ready

        // ---- screen GEMM (8 warps x 16 rows), 2 chunks per iter ----
        uint32_t ah[4][4];
#pragma unroll
        for (int s = 0; s < 4; s++)
            ldm4(ah[s], sbase + OFF_AH + SWZ(rowA * 128 + s * 32 + kaddA));

        const float xx0 = sxx[rrow0];
        const float xx1 = sxx[rrow1];
        float dmin0 = __int_as_float(0x7f800000);
        float dmin1 = __int_as_float(0x7f800000);

#pragma unroll 1
        for (int c = 0; c < NCHUNK; c += 2) {
            const int n0 = c * 16;
            const int n1 = n0 + 16;
            float acc0[4] = {0.f, 0.f, 0.f, 0.f};
            float acc1[4] = {0.f, 0.f, 0.f, 0.f};
            float acc2[4] = {0.f, 0.f, 0.f, 0.f};
            float acc3[4] = {0.f, 0.f, 0.f, 0.f};
#pragma unroll
            for (int s = 0; s < 4; s++) {
                uint32_t bh0[4], bh1[4];
                ldm4(bh0, sbase + OFF_BH + SWZ((n0 + rowB) * 128 + s * 32 + kaddB));
                ldm4(bh1, sbase + OFF_BH + SWZ((n1 + rowB) * 128 + s * 32 + kaddB));
                mma16816(acc0, ah[s], bh0 + 0);
                mma16816(acc1, ah[s], bh0 + 2);
                mma16816(acc2, ah[s], bh1 + 0);
                mma16816(acc3, ah[s], bh1 + 2);
            }
#pragma unroll
            for (int half = 0; half < 2; half++) {
                const int nb = half ? n1 : n0;
                const int cc = c + half;
                float* a0 = half ? acc2 : acc0;
                float* a1 = half ? acc3 : acc1;
                const int c0 = nb + jcol;
                const int c2 = nb + jcol + 8;
                float4 e00 = eew[c0];
                float4 e01 = eew[c0 + 1];
                float4 e10 = eew[c2];
                float4 e11 = eew[c2 + 1];
                float w2a = -2.f * e00.y, w2b = -2.f * e01.y;
                float w2c = -2.f * e10.y, w2d = -2.f * e11.y;
                float d00 = fmaf(a0[0], w2a, (xx0 + e00.x) * e00.y);
                float d01 = fmaf(a0[1], w2b, (xx0 + e01.x) * e01.y);
                float d02 = fmaf(a1[0], w2c, (xx0 + e10.x) * e10.y);
                float d03 = fmaf(a1[1], w2d, (xx0 + e11.x) * e11.y);
                float d10 = fmaf(a0[2], w2a, (xx1 + e00.x) * e00.y);
                float d11 = fmaf(a0[3], w2b, (xx1 + e01.x) * e01.y);
                float d12 = fmaf(a1[2], w2c, (xx1 + e10.x) * e10.y);
                float d13 = fmaf(a1[3], w2d, (xx1 + e11.x) * e11.y);

                // lane-local top-2 (value, code) for each row
                float m1 = d00; int k1 = c0; float m2 = d01;
                if (d01 < m1) { m2 = m1; m1 = d01; k1 = c0 + 1; }
                if (d02 < m1) { m2 = m1; m1 = d02; k1 = c2; } else m2 = fminf(m2, d02);
                if (d03 < m1) { m2 = m1; m1 = d03; k1 = c2 + 1; } else m2 = fminf(m2, d03);
                float p1 = d10; int l1 = c0; float p2 = d11;
                if (d11 < p1) { p2 = p1; p1 = d11; l1 = c0 + 1; }
                if (d12 < p1) { p2 = p1; p1 = d12; l1 = c2; } else p2 = fminf(p2, d12);
                if (d13 < p1) { p2 = p1; p1 = d13; l1 = c2 + 1; } else p2 = fminf(p2, d13);

                // merge across the 4 lanes of the row-group
#pragma unroll
                for (int off = 1; off <= 2; off <<= 1) {
                    float om1 = __shfl_xor_sync(0xffffffffu, m1, off);
                    int   ok1 = __shfl_xor_sync(0xffffffffu, k1, off);
                    float om2 = __shfl_xor_sync(0xffffffffu, m2, off);
                    if (om1 < m1) { m2 = fminf(m1, om2); m1 = om1; k1 = ok1; }
                    else          { m2 = fminf(m2, om1); }
                    float op1 = __shfl_xor_sync(0xffffffffu, p1, off);
                    int   ol1 = __shfl_xor_sync(0xffffffffu, l1, off);
                    float op2 = __shfl_xor_sync(0xffffffffu, p2, off);
                    if (op1 < p1) { p2 = fminf(p1, op2); p1 = op1; l1 = ol1; }
                    else          { p2 = fminf(p2, op1); }
                }
                dmin0 = fminf(dmin0, m1);
                dmin1 = fminf(dmin1, p1);
                if ((lane & 3) == 0) {
                    cmin[rrow0 * CMIN_STRIDE + cc] = m1;
                    cmin[rrow1 * CMIN_STRIDE + cc] = p1;
                    // m2 stored fp16, padded DOWN (conservative)
                    float m2p = m2 - fmaf(fabsf(m2), 2.5e-3f, 1e-5f);
                    float p2p = p2 - fmaf(fabsf(p2), 2.5e-3f, 1e-5f);
                    caux[rrow0 * CMIN_STRIDE + cc] =
                        ((uint32_t)__half_as_ushort(__float2half_rn(m2p)) << 16) |
                        (uint32_t)k1;
                    caux[rrow1 * CMIN_STRIDE + cc] =
                        ((uint32_t)__half_as_ushort(__float2half_rn(p2p)) << 16) |
                        (uint32_t)l1;
                }
            }
        }
        if ((lane & 3) == 0) {
            trow[rrow0] = dmin0;
            trow[rrow1] = dmin1;
        }
        __syncthreads();  // cmin/caux/trow ready

        // ---- phase 2a: per-row classify; singleton -> direct answer ----
        if (tid < TILE_M) {
            float errmax = fmaf(2.5e-3f, sqrtf(sxx[tid]) * smax, 1e-2f);
            float thr = trow[tid] + 2.f * errmax;
            uint32_t mask = 0;
            bool amb = false;
            uint32_t k1 = 0;
#pragma unroll 1
            for (int c = 0; c < NCHUNK; c++) {
                if (cmin[tid * CMIN_STRIDE + c] <= thr) {
                    mask |= (1u << c);
                    uint32_t a = caux[tid * CMIN_STRIDE + c];
                    k1 = a & 0x1ffu;
                    float m2 = __half2float(__ushort_as_half((unsigned short)(a >> 16)));
                    if (m2 <= thr) amb = true;
                }
            }
            if (!amb && __popc(mask) == 1) {
                // singleton: screen argmin provably exact (strict margin)
                best64[tid] = (u64)k1;
            } else {
                best64[tid] = 0xFFFFFFFFFFFFFFFFull;
                while (mask) {
                    int c = __ffs(mask) - 1;
                    mask &= mask - 1;
                    int slot = atomicAdd(qn, 1);
                    if (slot < QCAP)
                        queue[slot] = ((uint32_t)tid << 5) | (uint32_t)c;
                }
            }
        }
        __syncthreads();  // queue + best init ready

        // ---- staged warp rescore of ambiguous chunks (exact fp32) ----
        {
            int nent = *qn;
            if (nent > QCAP) nent = QCAP;
            float4* stg = (float4*)(smem + OFF_STAGE + wid * STG_STRIDE);
#pragma unroll 1
            for (int e = wid; e < nent; e += 8) {
                uint32_t ent = queue[e];
                int row = (int)(ent >> 5);
                int c = (int)(ent & 31);
                const float4* src = (const float4*)(emb + (c << 10));
#pragma unroll
                for (int j = 0; j < 8; j++) {
                    float4 v = __ldg(src + j * 32 + lane);
                    int jj = j * 32 + lane;
                    stg[(jj >> 4) * 17 + (jj & 15)] = v;
                }
                __syncwarp();
                u64 key = 0xFFFFFFFFFFFFFFFFull;
                if (lane < 16) {
                    const float4* xs = (const float4*)(smem + OFF_X + row * XSTRIDE);
                    const float4* ep = stg + lane * 17;
                    float s0 = 0.f, s1 = 0.f, s2 = 0.f, s3 = 0.f;
#pragma unroll
                    for (int q = 0; q < 16; q++) {
                        float4 e4 = ep[q];
                        float4 x4 = xs[q];
                        s0 = fmaf(x4.x, e4.x, s0);
                        s1 = fmaf(x4.y, e4.y, s1);
                        s2 = fmaf(x4.z, e4.z, s2);
                        s3 = fmaf(x4.w, e4.w, s3);
                    }
                    float d = (s0 + s1) + (s2 + s3);
                    int k = (c << 4) + lane;
                    float4 ew = eew[k];
                    float t = (sxx[row] + ew.x - 2.0f * d) * ew.y;
                    key = ((u64)__float_as_uint(t) << 32) | (unsigned)k;
                }
#pragma unroll
                for (int off = 16; off > 0; off >>= 1) {
                    u64 o = __shfl_xor_sync(0xffffffffu, key, off);
                    if (o < key) key = o;
                }
                if (lane == 0) atomicMin(&best64[row], key);
                __syncwarp();
            }
        }
        __syncthreads();  // best ready

        // ---- outputs: coalesced cooperative write + loss ----
        for (int idx = tid; idx < TILE_M * 16; idx += TPB) {
            int row = idx >> 4, q = idx & 15;
            int bk = (int)(best64[row] & 0x1ff);
            float4 e4 = __ldg((const float4*)(emb + bk * DIM) + q);
            float4 x4 = *(const float4*)(smem + OFF_X + row * XSTRIDE + q * 16);
            float dx = x4.x - e4.x, dy = x4.y - e4.y;
            float dz = x4.z - e4.z, dw = x4.w - e4.w;
            lsum += dx * dx + dy * dy + dz * dz + dw * dw;
            *((float4*)(out_q + (base + row) * DIM) + q) = e4;
            if (q == 0) out_idx[base + row] = (float)bk;
        }
    }

    // ---- loss block reduction ----
    __syncthreads();
    float* red = (float*)(smem + OFF_RED);
    red[tid] = lsum;
    __syncthreads();
#pragma unroll
    for (int s = TPB / 2; s > 0; s >>= 1) {
        if (tid < s) red[tid] += red[tid + s];
        __syncthreads();
    }

    // ---- last-CTA finalize (deterministic ordered sum) ----
    __shared__ unsigned int s_ticket;
    if (tid == 0) {
        atomicExch(&g_part[blockIdx.x], red[0]);
        __threadfence();
        s_ticket = atomicAdd(&g_ticket, 1u);
    }
    __syncthreads();
    if ((s_ticket % gridDim.x) == gridDim.x - 1) {
        __threadfence();
        if (tid < (int)gridDim.x) red[tid] = atomicAdd(&g_part[tid], 0.0f);
        __syncthreads();
        if (tid == 0) {
            float s = 0.f;
            for (int i = 0; i < (int)gridDim.x; i++) s += red[i];
            out_loss[0] = 0.25f * s * inv_count;
        }
    }
}

extern "C" void kernel_launch(void* const* d_in, const int* in_sizes, int n_in,
                              void* d_out, int out_size) {
    const float* inputs = (const float*)d_in[0];
    const float* emb    = (const float*)d_in[1];
    const float* ema    = (const float*)d_in[2];

    int N = in_sizes[0] / DIM;
    int ntiles = N / TILE_M;
    float* out = (float*)d_out;
    float* out_q    = out;
    float* out_loss = out + (size_t)N * DIM;
    float* out_idx  = out + (size_t)N * DIM + 1;

    static int grid = 0;
    if (grid == 0) {
        int sms = 0;
        cudaDeviceGetAttribute(&sms, cudaDevAttrMultiProcessorCount, 0);
        grid = (sms > 0 && sms <= MAXGRID) ? sms : 148;
        cudaFuncSetAttribute(vq_hmma, cudaFuncAttributeMaxDynamicSharedMemorySize,
                             SMEM_TOTAL);
    }

    vq_hmma<<<grid, TPB, SMEM_TOTAL>>>(inputs, emb, ema, out_q, out_idx,
                                       out_loss, ntiles,
                                       1.0f / ((float)N * (float)DIM));
}

// round 14
// speedup vs baseline: 1.2363x; 1.2363x over previous
#include <cuda_runtime.h>
#include <cuda_fp16.h>
#include <math.h>
#include <stdint.h>

// VectorQuantizerEMA: D=64, K=512, N=B*T=262144.
// fp16 HMMA screen with warp-owns-codes tiling: B fragments live in registers
// across ALL tiles (zero B-LDSM per tile). Round-11 phase2a/rescore verbatim.
#define DIM 64
#define NCODES 512
#define TILE_M 128
#define TPB 256
#define MAXGRID 256
#define NCHUNK 32
#define CMIN_STRIDE 33
#define QCAP 4096
#define XSTRIDE 272
#define STG_STRIDE 4352

__device__ float g_part[MAXGRID];
__device__ unsigned int g_ticket;

// ---------- smem layout (bytes) ----------
#define OFF_AH     0                   // A fp16 [128 x 128B] SW128      (16384)
#define OFF_BH     16384               // B fp16 [512 x 128B] SW128      (65536)
#define OFF_X      81920               // x fp32 [128 x 272B]            (34816)
#define OFF_EEW    116736              // float4[512]: (ee, w, s, 0)     (8192)
#define OFF_CMIN   124928              // f32[128][33] chunk min         (16896)
#define OFF_CAUX   141824              // u32[128][33] fp16(m2)<<16|k1   (16896)
#define OFF_SXX    158720              // f32[128]                       (512)
#define OFF_BEST   159232              // u64[128]                       (1024)
#define OFF_QUEUE  160256              // u32[QCAP]                      (16384)
#define OFF_CNT    176640              // qn @+0, smax @+8               (16)
#define OFF_STAGE  176656              // 8 warps x 4352B                (34816)
#define OFF_RED    211472              // float[256]                     (1024)
#define SMEM_TOTAL 212496

#define SWZ(o) ((uint32_t)(o) ^ ((((uint32_t)(o)) >> 3) & 0x70))

typedef unsigned long long u64;

__device__ __forceinline__ uint32_t smem_u32(const void* p) {
    uint32_t a;
    asm("{ .reg .u64 t; cvta.to.shared.u64 t, %1; cvt.u32.u64 %0, t; }"
        : "=r"(a) : "l"(p));
    return a;
}
__device__ __forceinline__ void ldm4(uint32_t* r, uint32_t addr) {
    asm volatile("ldmatrix.sync.aligned.m8n8.x4.shared.b16 {%0,%1,%2,%3}, [%4];"
                 : "=r"(r[0]), "=r"(r[1]), "=r"(r[2]), "=r"(r[3]) : "r"(addr));
}
__device__ __forceinline__ void mma16816(float* c, const uint32_t* a,
                                         const uint32_t* b) {
    asm volatile(
        "mma.sync.aligned.m16n8k16.row.col.f32.f16.f16.f32 "
        "{%0,%1,%2,%3}, {%4,%5,%6,%7}, {%8,%9}, {%0,%1,%2,%3};"
        : "+f"(c[0]), "+f"(c[1]), "+f"(c[2]), "+f"(c[3])
        : "r"(a[0]), "r"(a[1]), "r"(a[2]), "r"(a[3]), "r"(b[0]), "r"(b[1]));
}
__device__ __forceinline__ uint32_t packh2(float a, float b) {
    __half2 h = __floats2half2_rn(a, b);
    return *(uint32_t*)&h;
}

__global__ void __launch_bounds__(TPB, 1)
vq_hmma(const float* __restrict__ inputs,
        const float* __restrict__ emb,
        const float* __restrict__ ema,
        float* __restrict__ out_q,
        float* __restrict__ out_idx,
        float* __restrict__ out_loss,
        int ntiles, float inv_count) {
    extern __shared__ char smem[];
    const uint32_t sbase = smem_u32(smem);
    const int tid  = threadIdx.x;
    const int wid  = tid >> 5;
    const int lane = tid & 31;

    float4* eew   = (float4*)(smem + OFF_EEW);
    float*  cmin  = (float*)(smem + OFF_CMIN);
    uint32_t* caux = (uint32_t*)(smem + OFF_CAUX);
    float*  sxx   = (float*)(smem + OFF_SXX);
    u64*    best64 = (u64*)(smem + OFF_BEST);
    uint32_t* queue = (uint32_t*)(smem + OFF_QUEUE);
    int* qn = (int*)(smem + OFF_CNT);

    if (tid == 0) *(int*)(smem + OFF_CNT + 8) = 0;
    __syncthreads();

    // ---- codebook init: fp16 plane + (ee, w, s); ee = serial fma chain ----
    for (int k = tid; k < NCODES; k += TPB) {
        const float* e = emb + k * DIM;
        float ee = 0.f;
#pragma unroll
        for (int d = 0; d < DIM; d++) ee += e[d] * e[d];
        const float4* ep = (const float4*)e;
#pragma unroll
        for (int q = 0; q < 16; q++) {
            float4 e4 = ep[q];
            uint2 hv = make_uint2(packh2(e4.x, e4.y), packh2(e4.z, e4.w));
            *(uint2*)(smem + OFF_BH + SWZ(k * 128 + q * 8)) = hv;
        }
        float w = sqrtf(ema[k]);
        float s = sqrtf(ee) * w;
        eew[k] = make_float4(ee, w, s, 0.f);
        atomicMax((int*)(smem + OFF_CNT + 8), __float_as_int(s));  // s >= 0
    }
    __syncthreads();
    const float smax = *(float*)(smem + OFF_CNT + 8);

    // fragment geometry
    const int rowAoff = ((lane >> 3) & 1) * 8 + (lane & 7);   // within row-group
    const uint32_t kaddA = ((lane >> 4) & 1) * 16;
    const int rowB = ((lane >> 4) & 1) * 8 + (lane & 7);
    const uint32_t kaddB = ((lane >> 3) & 1) * 16;
    const int rsub = lane >> 2;          // epilogue row within group (0..7)
    const int jcol = (lane & 3) * 2;     // epilogue col pair within chunk

    // ---- B fragments: this warp's 4 chunks, ALL tiles, in registers ----
    // chunk ci = wid*4 + i, codes [ci*16, ci*16+16)
    uint32_t bf[4][4][4];
#pragma unroll
    for (int i = 0; i < 4; i++) {
        const int nb = (wid * 4 + i) * 16;
#pragma unroll
        for (int s = 0; s < 4; s++)
            ldm4(bf[i][s], sbase + OFF_BH + SWZ((nb + rowB) * 128 + s * 32 + kaddB));
    }

    float lsum = 0.f;

    for (int tile = blockIdx.x; tile < ntiles; tile += gridDim.x) {
        const size_t base = (size_t)tile * TILE_M;
        __syncthreads();  // prev tile fully consumed

        // ---- A-build: x -> smem fp32 (padded) + fp16 plane ----
        if (tid < TILE_M) {
            const float4* xp = (const float4*)(inputs + (base + tid) * DIM);
            float4* xs = (float4*)(smem + OFF_X + tid * XSTRIDE);
            float xxr = 0.f;
#pragma unroll
            for (int q = 0; q < 16; q++) {
                float4 v = xp[q];
                xs[q] = v;
                xxr += v.x * v.x + v.y * v.y + v.z * v.z + v.w * v.w;
                uint2 hv = make_uint2(packh2(v.x, v.y), packh2(v.z, v.w));
                *(uint2*)(smem + OFF_AH + SWZ(tid * 128 + q * 8)) = hv;
            }
            sxx[tid] = xxr;
        }
        if (tid == 0) *qn = 0;
        __syncthreads();  // A ready

        // ---- screen: 8 row-groups x (this warp's 4 chunks) ----
#pragma unroll 1
        for (int rg = 0; rg < 8; rg++) {
            const int rbase = rg * 16;
            uint32_t ah[4][4];
#pragma unroll
            for (int s = 0; s < 4; s++)
                ldm4(ah[s], sbase + OFF_AH +
                            SWZ((rbase + rowAoff) * 128 + s * 32 + kaddA));

            const int rrow0 = rbase + rsub;
            const int rrow1 = rrow0 + 8;
            const float xx0 = sxx[rrow0];
            const float xx1 = sxx[rrow1];

#pragma unroll
            for (int i = 0; i < 4; i++) {
                const int cc = wid * 4 + i;
                const int nb = cc * 16;
                float acc0[4] = {0.f, 0.f, 0.f, 0.f};
                float acc1[4] = {0.f, 0.f, 0.f, 0.f};
#pragma unroll
                for (int s = 0; s < 4; s++) {
                    mma16816(acc0, ah[s], bf[i][s] + 0);
                    mma16816(acc1, ah[s], bf[i][s] + 2);
                }
                const int c0 = nb + jcol;
                const int c2 = nb + jcol + 8;
                float4 e00 = eew[c0];
                float4 e01 = eew[c0 + 1];
                float4 e10 = eew[c2];
                float4 e11 = eew[c2 + 1];
                float w2a = -2.f * e00.y, w2b = -2.f * e01.y;
                float w2c = -2.f * e10.y, w2d = -2.f * e11.y;
                float d00 = fmaf(acc0[0], w2a, (xx0 + e00.x) * e00.y);
                float d01 = fmaf(acc0[1], w2b, (xx0 + e01.x) * e01.y);
                float d02 = fmaf(acc1[0], w2c, (xx0 + e10.x) * e10.y);
                float d03 = fmaf(acc1[1], w2d, (xx0 + e11.x) * e11.y);
                float d10 = fmaf(acc0[2], w2a, (xx1 + e00.x) * e00.y);
                float d11 = fmaf(acc0[3], w2b, (xx1 + e01.x) * e01.y);
                float d12 = fmaf(acc1[2], w2c, (xx1 + e10.x) * e10.y);
                float d13 = fmaf(acc1[3], w2d, (xx1 + e11.x) * e11.y);

                // lane-local top-2 (value, code) for each row
                float m1 = d00; int k1 = c0; float m2 = d01;
                if (d01 < m1) { m2 = m1; m1 = d01; k1 = c0 + 1; }
                if (d02 < m1) { m2 = m1; m1 = d02; k1 = c2; } else m2 = fminf(m2, d02);
                if (d03 < m1) { m2 = m1; m1 = d03; k1 = c2 + 1; } else m2 = fminf(m2, d03);
                float p1 = d10; int l1 = c0; float p2 = d11;
                if (d11 < p1) { p2 = p1; p1 = d11; l1 = c0 + 1; }
                if (d12 < p1) { p2 = p1; p1 = d12; l1 = c2; } else p2 = fminf(p2, d12);
                if (d13 < p1) { p2 = p1; p1 = d13; l1 = c2 + 1; } else p2 = fminf(p2, d13);

                // merge across the 4 lanes of the row-group
#pragma unroll
                for (int off = 1; off <= 2; off <<= 1) {
                    float om1 = __shfl_xor_sync(0xffffffffu, m1, off);
                    int   ok1 = __shfl_xor_sync(0xffffffffu, k1, off);
                    float om2 = __shfl_xor_sync(0xffffffffu, m2, off);
                    if (om1 < m1) { m2 = fminf(m1, om2); m1 = om1; k1 = ok1; }
                    else          { m2 = fminf(m2, om1); }
                    float op1 = __shfl_xor_sync(0xffffffffu, p1, off);
                    int   ol1 = __shfl_xor_sync(0xffffffffu, l1, off);
                    float op2 = __shfl_xor_sync(0xffffffffu, p2, off);
                    if (op1 < p1) { p2 = fminf(p1, op2); p1 = op1; l1 = ol1; }
                    else          { p2 = fminf(p2, op1); }
                }
                if ((lane & 3) == 0) {
                    cmin[rrow0 * CMIN_STRIDE + cc] = m1;
                    cmin[rrow1 * CMIN_STRIDE + cc] = p1;
                    float m2p = m2 - fmaf(fabsf(m2), 2.5e-3f, 1e-5f);
                    float p2p = p2 - fmaf(fabsf(p2), 2.5e-3f, 1e-5f);
                    caux[rrow0 * CMIN_STRIDE + cc] =
                        ((uint32_t)__half_as_ushort(__float2half_rn(m2p)) << 16) |
                        (uint32_t)k1;
                    caux[rrow1 * CMIN_STRIDE + cc] =
                        ((uint32_t)__half_as_ushort(__float2half_rn(p2p)) << 16) |
                        (uint32_t)l1;
                }
            }
        }
        __syncthreads();  // cmin/caux ready (cross-warp)

        // ---- phase 2a (round-11 style): row mins + ballot enqueue ----
        {
            const int rrow0 = wid * 16 + rsub;
            const int rrow1 = rrow0 + 8;
            // row mins via 4-lane cooperative scan
            float t0 = __int_as_float(0x7f800000);
            float t1 = __int_as_float(0x7f800000);
#pragma unroll
            for (int c = (lane & 3); c < NCHUNK; c += 4) {
                t0 = fminf(t0, cmin[rrow0 * CMIN_STRIDE + c]);
                t1 = fminf(t1, cmin[rrow1 * CMIN_STRIDE + c]);
            }
            t0 = fminf(t0, __shfl_xor_sync(0xffffffffu, t0, 1));
            t0 = fminf(t0, __shfl_xor_sync(0xffffffffu, t0, 2));
            t1 = fminf(t1, __shfl_xor_sync(0xffffffffu, t1, 1));
            t1 = fminf(t1, __shfl_xor_sync(0xffffffffu, t1, 2));
            const float xx0 = sxx[rrow0];
            const float xx1 = sxx[rrow1];
            float thr0 = t0 + 2.f * fmaf(2.5e-3f, sqrtf(xx0) * smax, 1e-2f);
            float thr1 = t1 + 2.f * fmaf(2.5e-3f, sqrtf(xx1) * smax, 1e-2f);
            if (lane < 16) best64[wid * 16 + lane] = 0xFFFFFFFFFFFFFFFFull;
            __syncwarp();
#pragma unroll 1
            for (int c = (lane & 3); c < NCHUNK; c += 4) {
                float m10 = cmin[rrow0 * CMIN_STRIDE + c];
                float m11 = cmin[rrow1 * CMIN_STRIDE + c];
                uint32_t a0 = caux[rrow0 * CMIN_STRIDE + c];
                uint32_t a1v = caux[rrow1 * CMIN_STRIDE + c];
                bool f0 = m10 <= thr0;
                bool f1 = m11 <= thr1;
                float m20 = __half2float(__ushort_as_half((unsigned short)(a0 >> 16)));
                float m21 = __half2float(__ushort_as_half((unsigned short)(a1v >> 16)));
                bool ch0 = f0 && (m20 <= thr0);
                bool ch1 = f1 && (m21 <= thr1);
                unsigned bt0 = __ballot_sync(0xffffffffu, f0);
                unsigned bt1 = __ballot_sync(0xffffffffu, f1);
                int tot = __popc(bt0) + __popc(bt1);
                int bs = 0;
                if (lane == 0 && tot) bs = atomicAdd(qn, tot);
                bs = __shfl_sync(0xffffffffu, bs, 0);
                unsigned lt = (1u << lane) - 1u;
                if (f0) {
                    int s_ = bs + __popc(bt0 & lt);
                    queue[s_] = ch0 ? (0x80000000u | ((uint32_t)rrow0 << 5) | (uint32_t)c)
                                    : (((uint32_t)rrow0 << 16) | (a0 & 0xffffu));
                }
                if (f1) {
                    int s_ = bs + __popc(bt0) + __popc(bt1 & lt);
                    queue[s_] = ch1 ? (0x80000000u | ((uint32_t)rrow1 << 5) | (uint32_t)c)
                                    : (((uint32_t)rrow1 << 16) | (a1v & 0xffffu));
                }
            }
        }
        __syncthreads();  // queue complete

        const int nent = *qn;

        // ---- pass A: chunk entries, warp-per-entry staged exact rescore ----
        {
            float4* stg = (float4*)(smem + OFF_STAGE + wid * STG_STRIDE);
#pragma unroll 1
            for (int e = wid; e < nent; e += 8) {
                uint32_t ent = queue[e];
                if (!(ent & 0x80000000u)) continue;
                int row = (int)((ent >> 5) & 0x7f);
                int c = (int)(ent & 31);
                const float4* src = (const float4*)(emb + (c << 10));
#pragma unroll
                for (int j = 0; j < 8; j++) {
                    float4 v = __ldg(src + j * 32 + lane);
                    int jj = j * 32 + lane;
                    stg[(jj >> 4) * 17 + (jj & 15)] = v;
                }
                __syncwarp();
                u64 key = 0xFFFFFFFFFFFFFFFFull;
                if (lane < 16) {
                    const float4* xs = (const float4*)(smem + OFF_X + row * XSTRIDE);
                    const float4* ep = stg + lane * 17;
                    float s0 = 0.f, s1 = 0.f, s2 = 0.f, s3 = 0.f;
#pragma unroll
                    for (int q = 0; q < 16; q++) {
                        float4 e4 = ep[q];
                        float4 x4 = xs[q];
                        s0 = fmaf(x4.x, e4.x, s0);
                        s1 = fmaf(x4.y, e4.y, s1);
                        s2 = fmaf(x4.z, e4.z, s2);
                        s3 = fmaf(x4.w, e4.w, s3);
                    }
                    float d = (s0 + s1) + (s2 + s3);
                    int k = (c << 4) + lane;
                    float4 ew = eew[k];
                    float t = (sxx[row] + ew.x - 2.0f * d) * ew.y;
                    key = ((u64)__float_as_uint(t) << 32) | (unsigned)k;
                }
#pragma unroll
                for (int off = 16; off > 0; off >>= 1) {
                    u64 o = __shfl_xor_sync(0xffffffffu, key, off);
                    if (o < key) key = o;
                }
                if (lane == 0) atomicMin(&best64[row], key);
                __syncwarp();
            }
        }

        // ---- pass B: code entries, per-thread exact rescore ----
        for (int i = tid; i < nent; i += TPB) {
            uint32_t ent = queue[i];
            if (ent & 0x80000000u) continue;
            int row = (int)(ent >> 16);
            int k = (int)(ent & 0x1ff);
            const float4* ep = (const float4*)(emb + k * DIM);
            const float4* xs = (const float4*)(smem + OFF_X + row * XSTRIDE);
            float s0 = 0.f, s1 = 0.f, s2 = 0.f, s3 = 0.f;
#pragma unroll
            for (int q = 0; q < 16; q++) {
                float4 e4 = __ldg(ep + q);
                float4 x4 = xs[q];
                s0 = fmaf(x4.x, e4.x, s0);
                s1 = fmaf(x4.y, e4.y, s1);
                s2 = fmaf(x4.z, e4.z, s2);
                s3 = fmaf(x4.w, e4.w, s3);
            }
            float d = (s0 + s1) + (s2 + s3);
            float4 ew = eew[k];
            float t = (sxx[row] + ew.x - 2.0f * d) * ew.y;
            u64 key = ((u64)__float_as_uint(t) << 32) | (unsigned)k;
            atomicMin(&best64[row], key);
        }
        __syncthreads();  // best ready

        // ---- outputs: coalesced cooperative write + loss ----
        for (int idx = tid; idx < TILE_M * 16; idx += TPB) {
            int row = idx >> 4, q = idx & 15;
            int bk = (int)(best64[row] & 0x1ff);
            float4 e4 = __ldg((const float4*)(emb + bk * DIM) + q);
            float4 x4 = *(const float4*)(smem + OFF_X + row * XSTRIDE + q * 16);
            float dx = x4.x - e4.x, dy = x4.y - e4.y;
            float dz = x4.z - e4.z, dw = x4.w - e4.w;
            lsum += dx * dx + dy * dy + dz * dz + dw * dw;
            *((float4*)(out_q + (base + row) * DIM) + q) = e4;
            if (q == 0) out_idx[base + row] = (float)bk;
        }
    }

    // ---- loss block reduction ----
    __syncthreads();
    float* red = (float*)(smem + OFF_RED);
    red[tid] = lsum;
    __syncthreads();
#pragma unroll
    for (int s = TPB / 2; s > 0; s >>= 1) {
        if (tid < s) red[tid] += red[tid + s];
        __syncthreads();
    }

    // ---- last-CTA finalize (deterministic ordered sum) ----
    __shared__ unsigned int s_ticket;
    if (tid == 0) {
        atomicExch(&g_part[blockIdx.x], red[0]);
        __threadfence();
        s_ticket = atomicAdd(&g_ticket, 1u);
    }
    __syncthreads();
    if ((s_ticket % gridDim.x) == gridDim.x - 1) {
        __threadfence();
        if (tid < (int)gridDim.x) red[tid] = atomicAdd(&g_part[tid], 0.0f);
        __syncthreads();
        if (tid == 0) {
            float s = 0.f;
            for (int i = 0; i < (int)gridDim.x; i++) s += red[i];
            out_loss[0] = 0.25f * s * inv_count;
        }
    }
}

extern "C" void kernel_launch(void* const* d_in, const int* in_sizes, int n_in,
                              void* d_out, int out_size) {
    const float* inputs = (const float*)d_in[0];
    const float* emb    = (const float*)d_in[1];
    const float* ema    = (const float*)d_in[2];

    int N = in_sizes[0] / DIM;
    int ntiles = N / TILE_M;
    float* out = (float*)d_out;
    float* out_q    = out;
    float* out_loss = out + (size_t)N * DIM;
    float* out_idx  = out + (size_t)N * DIM + 1;

    static int grid = 0;
    if (grid == 0) {
        int sms = 0;
        cudaDeviceGetAttribute(&sms, cudaDevAttrMultiProcessorCount, 0);
        grid = (sms > 0 && sms <= MAXGRID) ? sms : 148;
        cudaFuncSetAttribute(vq_hmma, cudaFuncAttributeMaxDynamicSharedMemorySize,
                             SMEM_TOTAL);
    }

    vq_hmma<<<grid, TPB, SMEM_TOTAL>>>(inputs, emb, ema, out_q, out_idx,
                                       out_loss, ntiles,
                                       1.0f / ((float)N * (float)DIM));
}

// round 15
// speedup vs baseline: 1.2897x; 1.0432x over previous
#include <cuda_runtime.h>
#include <cuda_fp16.h>
#include <math.h>
#include <stdint.h>

// VectorQuantizerEMA: D=64, K=512, N=B*T=262144.
// fp16 HMMA screen, warp-owns-codes (2 chunks/warp, B frags in registers),
// TPB=512 for 4 warps/SMSP latency hiding. Round-11 phase2a/rescore logic.
#define DIM 64
#define NCODES 512
#define TILE_M 128
#define TPB 512
#define NWARP 16
#define MAXGRID 256
#define NCHUNK 32
#define CMIN_STRIDE 33
#define QCAP 4096
#define XSTRIDE 272
#define STG_STRIDE 4352

__device__ float g_part[MAXGRID];
__device__ unsigned int g_ticket;

// ---------- smem layout (bytes) ----------
#define OFF_AH     0                   // A fp16 [128 x 128B] SW128      (16384)
#define OFF_BH     16384               // B fp16 [512 x 128B] SW128      (65536)
#define OFF_X      81920               // x fp32 [128 x 272B]            (34816)
#define OFF_EEW    116736              // float4[512]: (ee, w, s, 0)     (8192)
#define OFF_CMIN   124928              // f32[128][33] chunk min         (16896)
#define OFF_CAUX   141824              // u32[128][33] fp16(m2)<<16|k1   (16896)
#define OFF_SXX    158720              // f32[128]                       (512)
#define OFF_BEST   159232              // u64[128]                       (1024)
#define OFF_QUEUE  160256              // u32[QCAP]                      (16384)
#define OFF_CNT    176640              // qn @+0, smax @+8               (16)
#define OFF_STAGE  176656              // 8 stage buffers x 4352B        (34816)
#define OFF_RED    211472              // float[512]                     (2048)
#define SMEM_TOTAL 213520

#define SWZ(o) ((uint32_t)(o) ^ ((((uint32_t)(o)) >> 3) & 0x70))

typedef unsigned long long u64;

__device__ __forceinline__ uint32_t smem_u32(const void* p) {
    uint32_t a;
    asm("{ .reg .u64 t; cvta.to.shared.u64 t, %1; cvt.u32.u64 %0, t; }"
        : "=r"(a) : "l"(p));
    return a;
}
__device__ __forceinline__ void ldm4(uint32_t* r, uint32_t addr) {
    asm volatile("ldmatrix.sync.aligned.m8n8.x4.shared.b16 {%0,%1,%2,%3}, [%4];"
                 : "=r"(r[0]), "=r"(r[1]), "=r"(r[2]), "=r"(r[3]) : "r"(addr));
}
__device__ __forceinline__ void mma16816(float* c, const uint32_t* a,
                                         const uint32_t* b) {
    asm volatile(
        "mma.sync.aligned.m16n8k16.row.col.f32.f16.f16.f32 "
        "{%0,%1,%2,%3}, {%4,%5,%6,%7}, {%8,%9}, {%0,%1,%2,%3};"
        : "+f"(c[0]), "+f"(c[1]), "+f"(c[2]), "+f"(c[3])
        : "r"(a[0]), "r"(a[1]), "r"(a[2]), "r"(a[3]), "r"(b[0]), "r"(b[1]));
}
__device__ __forceinline__ uint32_t packh2(float a, float b) {
    __half2 h = __floats2half2_rn(a, b);
    return *(uint32_t*)&h;
}

__global__ void __launch_bounds__(TPB, 1)
vq_hmma(const float* __restrict__ inputs,
        const float* __restrict__ emb,
        const float* __restrict__ ema,
        float* __restrict__ out_q,
        float* __restrict__ out_idx,
        float* __restrict__ out_loss,
        int ntiles, float inv_count) {
    extern __shared__ char smem[];
    const uint32_t sbase = smem_u32(smem);
    const int tid  = threadIdx.x;
    const int wid  = tid >> 5;
    const int lane = tid & 31;

    float4* eew   = (float4*)(smem + OFF_EEW);
    float*  cmin  = (float*)(smem + OFF_CMIN);
    uint32_t* caux = (uint32_t*)(smem + OFF_CAUX);
    float*  sxx   = (float*)(smem + OFF_SXX);
    u64*    best64 = (u64*)(smem + OFF_BEST);
    uint32_t* queue = (uint32_t*)(smem + OFF_QUEUE);
    int* qn = (int*)(smem + OFF_CNT);

    if (tid == 0) *(int*)(smem + OFF_CNT + 8) = 0;
    __syncthreads();

    // ---- codebook init: fp16 plane + (ee, w, s); ee = serial fma chain ----
    for (int k = tid; k < NCODES; k += TPB) {
        const float* e = emb + k * DIM;
        float ee = 0.f;
#pragma unroll
        for (int d = 0; d < DIM; d++) ee += e[d] * e[d];
        const float4* ep = (const float4*)e;
#pragma unroll
        for (int q = 0; q < 16; q++) {
            float4 e4 = ep[q];
            uint2 hv = make_uint2(packh2(e4.x, e4.y), packh2(e4.z, e4.w));
            *(uint2*)(smem + OFF_BH + SWZ(k * 128 + q * 8)) = hv;
        }
        float w = sqrtf(ema[k]);
        float s = sqrtf(ee) * w;
        eew[k] = make_float4(ee, w, s, 0.f);
        atomicMax((int*)(smem + OFF_CNT + 8), __float_as_int(s));  // s >= 0
    }
    __syncthreads();
    const float smax = *(float*)(smem + OFF_CNT + 8);

    // fragment geometry
    const int rowAoff = ((lane >> 3) & 1) * 8 + (lane & 7);   // within row-group
    const uint32_t kaddA = ((lane >> 4) & 1) * 16;
    const int rowB = ((lane >> 4) & 1) * 8 + (lane & 7);
    const uint32_t kaddB = ((lane >> 3) & 1) * 16;
    const int rsub = lane >> 2;          // epilogue row within group (0..7)
    const int jcol = (lane & 3) * 2;     // epilogue col pair within chunk

    // ---- B fragments: this warp's 2 chunks, ALL tiles, in registers ----
    uint32_t bf[2][4][4];
#pragma unroll
    for (int i = 0; i < 2; i++) {
        const int nb = (wid * 2 + i) * 16;
#pragma unroll
        for (int s = 0; s < 4; s++)
            ldm4(bf[i][s], sbase + OFF_BH + SWZ((nb + rowB) * 128 + s * 32 + kaddB));
    }

    float lsum = 0.f;

    for (int tile = blockIdx.x; tile < ntiles; tile += gridDim.x) {
        const size_t base = (size_t)tile * TILE_M;
        __syncthreads();  // prev tile fully consumed

        // ---- A-build: x -> smem fp32 (padded) + fp16 plane ----
        if (tid < TILE_M) {
            const float4* xp = (const float4*)(inputs + (base + tid) * DIM);
            float4* xs = (float4*)(smem + OFF_X + tid * XSTRIDE);
            float xxr = 0.f;
#pragma unroll
            for (int q = 0; q < 16; q++) {
                float4 v = xp[q];
                xs[q] = v;
                xxr += v.x * v.x + v.y * v.y + v.z * v.z + v.w * v.w;
                uint2 hv = make_uint2(packh2(v.x, v.y), packh2(v.z, v.w));
                *(uint2*)(smem + OFF_AH + SWZ(tid * 128 + q * 8)) = hv;
            }
            sxx[tid] = xxr;
        }
        if (tid == 0) *qn = 0;
        __syncthreads();  // A ready

        // ---- screen: 8 row-groups x (this warp's 2 chunks) ----
#pragma unroll 1
        for (int rg = 0; rg < 8; rg++) {
            const int rbase = rg * 16;
            uint32_t ah[4][4];
#pragma unroll
            for (int s = 0; s < 4; s++)
                ldm4(ah[s], sbase + OFF_AH +
                            SWZ((rbase + rowAoff) * 128 + s * 32 + kaddA));

            const int rrow0 = rbase + rsub;
            const int rrow1 = rrow0 + 8;
            const float xx0 = sxx[rrow0];
            const float xx1 = sxx[rrow1];

#pragma unroll
            for (int i = 0; i < 2; i++) {
                const int cc = wid * 2 + i;
                const int nb = cc * 16;
                float acc0[4] = {0.f, 0.f, 0.f, 0.f};
                float acc1[4] = {0.f, 0.f, 0.f, 0.f};
#pragma unroll
                for (int s = 0; s < 4; s++) {
                    mma16816(acc0, ah[s], bf[i][s] + 0);
                    mma16816(acc1, ah[s], bf[i][s] + 2);
                }
                const int c0 = nb + jcol;
                const int c2 = nb + jcol + 8;
                float4 e00 = eew[c0];
                float4 e01 = eew[c0 + 1];
                float4 e10 = eew[c2];
                float4 e11 = eew[c2 + 1];
                float w2a = -2.f * e00.y, w2b = -2.f * e01.y;
                float w2c = -2.f * e10.y, w2d = -2.f * e11.y;
                float d00 = fmaf(acc0[0], w2a, (xx0 + e00.x) * e00.y);
                float d01 = fmaf(acc0[1], w2b, (xx0 + e01.x) * e01.y);
                float d02 = fmaf(acc1[0], w2c, (xx0 + e10.x) * e10.y);
                float d03 = fmaf(acc1[1], w2d, (xx0 + e11.x) * e11.y);
                float d10 = fmaf(acc0[2], w2a, (xx1 + e00.x) * e00.y);
                float d11 = fmaf(acc0[3], w2b, (xx1 + e01.x) * e01.y);
                float d12 = fmaf(acc1[2], w2c, (xx1 + e10.x) * e10.y);
                float d13 = fmaf(acc1[3], w2d, (xx1 + e11.x) * e11.y);

                // lane-local top-2 (value, code) for each row
                float m1 = d00; int k1 = c0; float m2 = d01;
                if (d01 < m1) { m2 = m1; m1 = d01; k1 = c0 + 1; }
                if (d02 < m1) { m2 = m1; m1 = d02; k1 = c2; } else m2 = fminf(m2, d02);
                if (d03 < m1) { m2 = m1; m1 = d03; k1 = c2 + 1; } else m2 = fminf(m2, d03);
                float p1 = d10; int l1 = c0; float p2 = d11;
                if (d11 < p1) { p2 = p1; p1 = d11; l1 = c0 + 1; }
                if (d12 < p1) { p2 = p1; p1 = d12; l1 = c2; } else p2 = fminf(p2, d12);
                if (d13 < p1) { p2 = p1; p1 = d13; l1 = c2 + 1; } else p2 = fminf(p2, d13);

                // merge across the 4 lanes of the row-group
#pragma unroll
                for (int off = 1; off <= 2; off <<= 1) {
                    float om1 = __shfl_xor_sync(0xffffffffu, m1, off);
                    int   ok1 = __shfl_xor_sync(0xffffffffu, k1, off);
                    float om2 = __shfl_xor_sync(0xffffffffu, m2, off);
                    if (om1 < m1) { m2 = fminf(m1, om2); m1 = om1; k1 = ok1; }
                    else          { m2 = fminf(m2, om1); }
                    float op1 = __shfl_xor_sync(0xffffffffu, p1, off);
                    int   ol1 = __shfl_xor_sync(0xffffffffu, l1, off);
                    float op2 = __shfl_xor_sync(0xffffffffu, p2, off);
                    if (op1 < p1) { p2 = fminf(p1, op2); p1 = op1; l1 = ol1; }
                    else          { p2 = fminf(p2, op1); }
                }
                if ((lane & 3) == 0) {
                    cmin[rrow0 * CMIN_STRIDE + cc] = m1;
                    cmin[rrow1 * CMIN_STRIDE + cc] = p1;
                    float m2p = m2 - fmaf(fabsf(m2), 2.5e-3f, 1e-5f);
                    float p2p = p2 - fmaf(fabsf(p2), 2.5e-3f, 1e-5f);
                    caux[rrow0 * CMIN_STRIDE + cc] =
                        ((uint32_t)__half_as_ushort(__float2half_rn(m2p)) << 16) |
                        (uint32_t)k1;
                    caux[rrow1 * CMIN_STRIDE + cc] =
                        ((uint32_t)__half_as_ushort(__float2half_rn(p2p)) << 16) |
                        (uint32_t)l1;
                }
            }
        }
        __syncthreads();  // cmin/caux ready (cross-warp)

        // ---- phase 2a: 8 rows per warp; row mins + ballot enqueue ----
        {
            const int rrow = wid * 8 + rsub;    // 16 warps x 8 rows = 128
            float t0 = __int_as_float(0x7f800000);
#pragma unroll
            for (int c = (lane & 3); c < NCHUNK; c += 4)
                t0 = fminf(t0, cmin[rrow * CMIN_STRIDE + c]);
            t0 = fminf(t0, __shfl_xor_sync(0xffffffffu, t0, 1));
            t0 = fminf(t0, __shfl_xor_sync(0xffffffffu, t0, 2));
            const float xx0 = sxx[rrow];
            float thr = t0 + 2.f * fmaf(2.5e-3f, sqrtf(xx0) * smax, 1e-2f);
            if (lane < 8) best64[wid * 8 + lane] = 0xFFFFFFFFFFFFFFFFull;
            __syncwarp();
#pragma unroll 1
            for (int c = (lane & 3); c < NCHUNK; c += 4) {
                float m10 = cmin[rrow * CMIN_STRIDE + c];
                uint32_t a0 = caux[rrow * CMIN_STRIDE + c];
                bool f0 = m10 <= thr;
                float m20 = __half2float(__ushort_as_half((unsigned short)(a0 >> 16)));
                bool ch0 = f0 && (m20 <= thr);
                unsigned bt0 = __ballot_sync(0xffffffffu, f0);
                int tot = __popc(bt0);
                int bs = 0;
                if (lane == 0 && tot) bs = atomicAdd(qn, tot);
                bs = __shfl_sync(0xffffffffu, bs, 0);
                unsigned lt = (1u << lane) - 1u;
                if (f0) {
                    int s_ = bs + __popc(bt0 & lt);
                    queue[s_] = ch0 ? (0x80000000u | ((uint32_t)rrow << 5) | (uint32_t)c)
                                    : (((uint32_t)rrow << 16) | (a0 & 0xffffu));
                }
            }
        }
        __syncthreads();  // queue complete

        const int nent = *qn;

        // ---- pass A: chunk entries (warps 0-7 have stage buffers) ----
        if (wid < 8) {
            float4* stg = (float4*)(smem + OFF_STAGE + wid * STG_STRIDE);
#pragma unroll 1
            for (int e = wid; e < nent; e += 8) {
                uint32_t ent = queue[e];
                if (!(ent & 0x80000000u)) continue;
                int row = (int)((ent >> 5) & 0x7f);
                int c = (int)(ent & 31);
                const float4* src = (const float4*)(emb + (c << 10));
#pragma unroll
                for (int j = 0; j < 8; j++) {
                    float4 v = __ldg(src + j * 32 + lane);
                    int jj = j * 32 + lane;
                    stg[(jj >> 4) * 17 + (jj & 15)] = v;
                }
                __syncwarp();
                u64 key = 0xFFFFFFFFFFFFFFFFull;
                if (lane < 16) {
                    const float4* xs = (const float4*)(smem + OFF_X + row * XSTRIDE);
                    const float4* ep = stg + lane * 17;
                    float s0 = 0.f, s1 = 0.f, s2 = 0.f, s3 = 0.f;
#pragma unroll
                    for (int q = 0; q < 16; q++) {
                        float4 e4 = ep[q];
                        float4 x4 = xs[q];
                        s0 = fmaf(x4.x, e4.x, s0);
                        s1 = fmaf(x4.y, e4.y, s1);
                        s2 = fmaf(x4.z, e4.z, s2);
                        s3 = fmaf(x4.w, e4.w, s3);
                    }
                    float d = (s0 + s1) + (s2 + s3);
                    int k = (c << 4) + lane;
                    float4 ew = eew[k];
                    float t = (sxx[row] + ew.x - 2.0f * d) * ew.y;
                    key = ((u64)__float_as_uint(t) << 32) | (unsigned)k;
                }
#pragma unroll
                for (int off = 16; off > 0; off >>= 1) {
                    u64 o = __shfl_xor_sync(0xffffffffu, key, off);
                    if (o < key) key = o;
                }
                if (lane == 0) atomicMin(&best64[row], key);
                __syncwarp();
            }
        }

        // ---- pass B: code entries, per-thread exact rescore ----
        for (int i = tid; i < nent; i += TPB) {
            uint32_t ent = queue[i];
            if (ent & 0x80000000u) continue;
            int row = (int)(ent >> 16);
            int k = (int)(ent & 0x1ff);
            const float4* ep = (const float4*)(emb + k * DIM);
            const float4* xs = (const float4*)(smem + OFF_X + row * XSTRIDE);
            float s0 = 0.f, s1 = 0.f, s2 = 0.f, s3 = 0.f;
#pragma unroll
            for (int q = 0; q < 16; q++) {
                float4 e4 = __ldg(ep + q);
                float4 x4 = xs[q];
                s0 = fmaf(x4.x, e4.x, s0);
                s1 = fmaf(x4.y, e4.y, s1);
                s2 = fmaf(x4.z, e4.z, s2);
                s3 = fmaf(x4.w, e4.w, s3);
            }
            float d = (s0 + s1) + (s2 + s3);
            float4 ew = eew[k];
            float t = (sxx[row] + ew.x - 2.0f * d) * ew.y;
            u64 key = ((u64)__float_as_uint(t) << 32) | (unsigned)k;
            atomicMin(&best64[row], key);
        }
        __syncthreads();  // best ready

        // ---- outputs: coalesced cooperative write + loss ----
        for (int idx = tid; idx < TILE_M * 16; idx += TPB) {
            int row = idx >> 4, q = idx & 15;
            int bk = (int)(best64[row] & 0x1ff);
            float4 e4 = __ldg((const float4*)(emb + bk * DIM) + q);
            float4 x4 = *(const float4*)(smem + OFF_X + row * XSTRIDE + q * 16);
            float dx = x4.x - e4.x, dy = x4.y - e4.y;
            float dz = x4.z - e4.z, dw = x4.w - e4.w;
            lsum += dx * dx + dy * dy + dz * dz + dw * dw;
            *((float4*)(out_q + (base + row) * DIM) + q) = e4;
            if (q == 0) out_idx[base + row] = (float)bk;
        }
    }

    // ---- loss block reduction ----
    __syncthreads();
    float* red = (float*)(smem + OFF_RED);
    red[tid] = lsum;
    __syncthreads();
#pragma unroll
    for (int s = TPB / 2; s > 0; s >>= 1) {
        if (tid < s) red[tid] += red[tid + s];
        __syncthreads();
    }

    // ---- last-CTA finalize (deterministic ordered sum) ----
    __shared__ unsigned int s_ticket;
    if (tid == 0) {
        atomicExch(&g_part[blockIdx.x], red[0]);
        __threadfence();
        s_ticket = atomicAdd(&g_ticket, 1u);
    }
    __syncthreads();
    if ((s_ticket % gridDim.x) == gridDim.x - 1) {
        __threadfence();
        if (tid < (int)gridDim.x) red[tid] = atomicAdd(&g_part[tid], 0.0f);
        __syncthreads();
        if (tid == 0) {
            float s = 0.f;
            for (int i = 0; i < (int)gridDim.x; i++) s += red[i];
            out_loss[0] = 0.25f * s * inv_count;
        }
    }
}

extern "C" void kernel_launch(void* const* d_in, const int* in_sizes, int n_in,
                              void* d_out, int out_size) {
    const float* inputs = (const float*)d_in[0];
    const float* emb    = (const float*)d_in[1];
    const float* ema    = (const float*)d_in[2];

    int N = in_sizes[0] / DIM;
    int ntiles = N / TILE_M;
    float* out = (float*)d_out;
    float* out_q    = out;
    float* out_loss = out + (size_t)N * DIM;
    float* out_idx  = out + (size_t)N * DIM + 1;

    static int grid = 0;
    if (grid == 0) {
        int sms = 0;
        cudaDeviceGetAttribute(&sms, cudaDevAttrMultiProcessorCount, 0);
        grid = (sms > 0 && sms <= MAXGRID) ? sms : 148;
        cudaFuncSetAttribute(vq_hmma, cudaFuncAttributeMaxDynamicSharedMemorySize,
                             SMEM_TOTAL);
    }

    vq_hmma<<<grid, TPB, SMEM_TOTAL>>>(inputs, emb, ema, out_q, out_idx,
                                       out_loss, ntiles,
                                       1.0f / ((float)N * (float)DIM));
}

// round 16
// speedup vs baseline: 1.3352x; 1.0353x over previous
#include <cuda_runtime.h>
#include <cuda_fp16.h>
#include <math.h>
#include <stdint.h>

// VectorQuantizerEMA: D=64, K=512, N=B*T=262144.
// fp16 HMMA screen, warp-owns-codes (2 chunks/warp, B frags in registers),
// TPB=512. Epilogue diet: (w, ee*w) table -> 2-fma distances + LDS.64,
// __float2half_rd for conservative m2. Candidate logic identical to R15.
#define DIM 64
#define NCODES 512
#define TILE_M 128
#define TPB 512
#define NWARP 16
#define MAXGRID 256
#define NCHUNK 32
#define CMIN_STRIDE 33
#define QCAP 4096
#define XSTRIDE 272
#define STG_STRIDE 4352

__device__ float g_part[MAXGRID];
__device__ unsigned int g_ticket;

// ---------- smem layout (bytes) ----------
#define OFF_AH     0                   // A fp16 [128 x 128B] SW128      (16384)
#define OFF_BH     16384               // B fp16 [512 x 128B] SW128      (65536)
#define OFF_X      81920               // x fp32 [128 x 272B]            (34816)
#define OFF_EEW    116736              // float4[512]: (ee, w, s, 0)     (8192)
#define OFF_SEW    124928              // float2[512]: (w, ee*w)         (4096)
#define OFF_CMIN   129024              // f32[128][33] chunk min         (16896)
#define OFF_CAUX   145920              // u32[128][33] fp16(m2)<<16|k1   (16896)
#define OFF_SXX    162816              // f32[128]                       (512)
#define OFF_BEST   163328              // u64[128]                       (1024)
#define OFF_QUEUE  164352              // u32[QCAP]                      (16384)
#define OFF_CNT    180736              // qn @+0, smax @+8               (16)
#define OFF_STAGE  180752              // 8 stage buffers x 4352B        (34816)
#define OFF_RED    215568              // float[512]                     (2048)
#define SMEM_TOTAL 217616

#define SWZ(o) ((uint32_t)(o) ^ ((((uint32_t)(o)) >> 3) & 0x70))

typedef unsigned long long u64;

__device__ __forceinline__ uint32_t smem_u32(const void* p) {
    uint32_t a;
    asm("{ .reg .u64 t; cvta.to.shared.u64 t, %1; cvt.u32.u64 %0, t; }"
        : "=r"(a) : "l"(p));
    return a;
}
__device__ __forceinline__ void ldm4(uint32_t* r, uint32_t addr) {
    asm volatile("ldmatrix.sync.aligned.m8n8.x4.shared.b16 {%0,%1,%2,%3}, [%4];"
                 : "=r"(r[0]), "=r"(r[1]), "=r"(r[2]), "=r"(r[3]) : "r"(addr));
}
__device__ __forceinline__ void mma16816(float* c, const uint32_t* a,
                                         const uint32_t* b) {
    asm volatile(
        "mma.sync.aligned.m16n8k16.row.col.f32.f16.f16.f32 "
        "{%0,%1,%2,%3}, {%4,%5,%6,%7}, {%8,%9}, {%0,%1,%2,%3};"
        : "+f"(c[0]), "+f"(c[1]), "+f"(c[2]), "+f"(c[3])
        : "r"(a[0]), "r"(a[1]), "r"(a[2]), "r"(a[3]), "r"(b[0]), "r"(b[1]));
}
__device__ __forceinline__ uint32_t packh2(float a, float b) {
    __half2 h = __floats2half2_rn(a, b);
    return *(uint32_t*)&h;
}

__global__ void __launch_bounds__(TPB, 1)
vq_hmma(const float* __restrict__ inputs,
        const float* __restrict__ emb,
        const float* __restrict__ ema,
        float* __restrict__ out_q,
        float* __restrict__ out_idx,
        float* __restrict__ out_loss,
        int ntiles, float inv_count) {
    extern __shared__ char smem[];
    const uint32_t sbase = smem_u32(smem);
    const int tid  = threadIdx.x;
    const int wid  = tid >> 5;
    const int lane = tid & 31;

    float4* eew   = (float4*)(smem + OFF_EEW);
    float2* sew   = (float2*)(smem + OFF_SEW);
    float*  cmin  = (float*)(smem + OFF_CMIN);
    uint32_t* caux = (uint32_t*)(smem + OFF_CAUX);
    float*  sxx   = (float*)(smem + OFF_SXX);
    u64*    best64 = (u64*)(smem + OFF_BEST);
    uint32_t* queue = (uint32_t*)(smem + OFF_QUEUE);
    int* qn = (int*)(smem + OFF_CNT);

    if (tid == 0) *(int*)(smem + OFF_CNT + 8) = 0;
    __syncthreads();

    // ---- codebook init: fp16 plane + (ee, w, s) + (w, ee*w) ----
    for (int k = tid; k < NCODES; k += TPB) {
        const float* e = emb + k * DIM;
        float ee = 0.f;
#pragma unroll
        for (int d = 0; d < DIM; d++) ee += e[d] * e[d];
        const float4* ep = (const float4*)e;
#pragma unroll
        for (int q = 0; q < 16; q++) {
            float4 e4 = ep[q];
            uint2 hv = make_uint2(packh2(e4.x, e4.y), packh2(e4.z, e4.w));
            *(uint2*)(smem + OFF_BH + SWZ(k * 128 + q * 8)) = hv;
        }
        float w = sqrtf(ema[k]);
        float s = sqrtf(ee) * w;
        eew[k] = make_float4(ee, w, s, 0.f);
        sew[k] = make_float2(w, ee * w);
        atomicMax((int*)(smem + OFF_CNT + 8), __float_as_int(s));  // s >= 0
    }
    __syncthreads();
    const float smax = *(float*)(smem + OFF_CNT + 8);

    // fragment geometry
    const int rowAoff = ((lane >> 3) & 1) * 8 + (lane & 7);   // within row-group
    const uint32_t kaddA = ((lane >> 4) & 1) * 16;
    const int rowB = ((lane >> 4) & 1) * 8 + (lane & 7);
    const uint32_t kaddB = ((lane >> 3) & 1) * 16;
    const int rsub = lane >> 2;          // epilogue row within group (0..7)
    const int jcol = (lane & 3) * 2;     // epilogue col pair within chunk

    // ---- B fragments: this warp's 2 chunks, ALL tiles, in registers ----
    uint32_t bf[2][4][4];
#pragma unroll
    for (int i = 0; i < 2; i++) {
        const int nb = (wid * 2 + i) * 16;
#pragma unroll
        for (int s = 0; s < 4; s++)
            ldm4(bf[i][s], sbase + OFF_BH + SWZ((nb + rowB) * 128 + s * 32 + kaddB));
    }

    float lsum = 0.f;

    for (int tile = blockIdx.x; tile < ntiles; tile += gridDim.x) {
        const size_t base = (size_t)tile * TILE_M;
        __syncthreads();  // prev tile fully consumed

        // ---- A-build: x -> smem fp32 (padded) + fp16 plane ----
        if (tid < TILE_M) {
            const float4* xp = (const float4*)(inputs + (base + tid) * DIM);
            float4* xs = (float4*)(smem + OFF_X + tid * XSTRIDE);
            float xxr = 0.f;
#pragma unroll
            for (int q = 0; q < 16; q++) {
                float4 v = xp[q];
                xs[q] = v;
                xxr += v.x * v.x + v.y * v.y + v.z * v.z + v.w * v.w;
                uint2 hv = make_uint2(packh2(v.x, v.y), packh2(v.z, v.w));
                *(uint2*)(smem + OFF_AH + SWZ(tid * 128 + q * 8)) = hv;
            }
            sxx[tid] = xxr;
        }
        if (tid == 0) *qn = 0;
        __syncthreads();  // A ready

        // ---- screen: 8 row-groups x (this warp's 2 chunks) ----
#pragma unroll 1
        for (int rg = 0; rg < 8; rg++) {
            const int rbase = rg * 16;
            uint32_t ah[4][4];
#pragma unroll
            for (int s = 0; s < 4; s++)
                ldm4(ah[s], sbase + OFF_AH +
                            SWZ((rbase + rowAoff) * 128 + s * 32 + kaddA));

            const int rrow0 = rbase + rsub;
            const int rrow1 = rrow0 + 8;
            const float xx0 = sxx[rrow0];
            const float xx1 = sxx[rrow1];

#pragma unroll
            for (int i = 0; i < 2; i++) {
                const int cc = wid * 2 + i;
                const int nb = cc * 16;
                float acc0[4] = {0.f, 0.f, 0.f, 0.f};
                float acc1[4] = {0.f, 0.f, 0.f, 0.f};
#pragma unroll
                for (int s = 0; s < 4; s++) {
                    mma16816(acc0, ah[s], bf[i][s] + 0);
                    mma16816(acc1, ah[s], bf[i][s] + 2);
                }
                const int c0 = nb + jcol;
                const int c2 = nb + jcol + 8;
                // (w, ee*w) table: d = fmaf(acc, -2w, fmaf(xx, w, eeW))
                float2 s00 = sew[c0];
                float2 s01 = sew[c0 + 1];
                float2 s10 = sew[c2];
                float2 s11 = sew[c2 + 1];
                float w2a = -(s00.x + s00.x);
                float w2b = -(s01.x + s01.x);
                float w2c = -(s10.x + s10.x);
                float w2d = -(s11.x + s11.x);
                float d00 = fmaf(acc0[0], w2a, fmaf(xx0, s00.x, s00.y));
                float d01 = fmaf(acc0[1], w2b, fmaf(xx0, s01.x, s01.y));
                float d02 = fmaf(acc1[0], w2c, fmaf(xx0, s10.x, s10.y));
                float d03 = fmaf(acc1[1], w2d, fmaf(xx0, s11.x, s11.y));
                float d10 = fmaf(acc0[2], w2a, fmaf(xx1, s00.x, s00.y));
                float d11 = fmaf(acc0[3], w2b, fmaf(xx1, s01.x, s01.y));
                float d12 = fmaf(acc1[2], w2c, fmaf(xx1, s10.x, s10.y));
                float d13 = fmaf(acc1[3], w2d, fmaf(xx1, s11.x, s11.y));

                // lane-local top-2 (value, code) for each row
                float m1 = d00; int k1 = c0; float m2 = d01;
                if (d01 < m1) { m2 = m1; m1 = d01; k1 = c0 + 1; }
                if (d02 < m1) { m2 = m1; m1 = d02; k1 = c2; } else m2 = fminf(m2, d02);
                if (d03 < m1) { m2 = m1; m1 = d03; k1 = c2 + 1; } else m2 = fminf(m2, d03);
                float p1 = d10; int l1 = c0; float p2 = d11;
                if (d11 < p1) { p2 = p1; p1 = d11; l1 = c0 + 1; }
                if (d12 < p1) { p2 = p1; p1 = d12; l1 = c2; } else p2 = fminf(p2, d12);
                if (d13 < p1) { p2 = p1; p1 = d13; l1 = c2 + 1; } else p2 = fminf(p2, d13);

                // merge across the 4 lanes of the row-group
#pragma unroll
                for (int off = 1; off <= 2; off <<= 1) {
                    float om1 = __shfl_xor_sync(0xffffffffu, m1, off);
                    int   ok1 = __shfl_xor_sync(0xffffffffu, k1, off);
                    float om2 = __shfl_xor_sync(0xffffffffu, m2, off);
                    if (om1 < m1) { m2 = fminf(m1, om2); m1 = om1; k1 = ok1; }
                    else          { m2 = fminf(m2, om1); }
                    float op1 = __shfl_xor_sync(0xffffffffu, p1, off);
                    int   ol1 = __shfl_xor_sync(0xffffffffu, l1, off);
                    float op2 = __shfl_xor_sync(0xffffffffu, p2, off);
                    if (op1 < p1) { p2 = fminf(p1, op2); p1 = op1; l1 = ol1; }
                    else          { p2 = fminf(p2, op1); }
                }
                if ((lane & 3) == 0) {
                    cmin[rrow0 * CMIN_STRIDE + cc] = m1;
                    cmin[rrow1 * CMIN_STRIDE + cc] = p1;
                    // directed round-down: stored m2 <= true m2 (conservative)
                    caux[rrow0 * CMIN_STRIDE + cc] =
                        ((uint32_t)__half_as_ushort(__float2half_rd(m2)) << 16) |
                        (uint32_t)k1;
                    caux[rrow1 * CMIN_STRIDE + cc] =
                        ((uint32_t)__half_as_ushort(__float2half_rd(p2)) << 16) |
                        (uint32_t)l1;
                }
            }
        }
        __syncthreads();  // cmin/caux ready (cross-warp)

        // ---- phase 2a: 8 rows per warp; row mins + ballot enqueue ----
        {
            const int rrow = wid * 8 + rsub;    // 16 warps x 8 rows = 128
            float t0 = __int_as_float(0x7f800000);
#pragma unroll
            for (int c = (lane & 3); c < NCHUNK; c += 4)
                t0 = fminf(t0, cmin[rrow * CMIN_STRIDE + c]);
            t0 = fminf(t0, __shfl_xor_sync(0xffffffffu, t0, 1));
            t0 = fminf(t0, __shfl_xor_sync(0xffffffffu, t0, 2));
            const float xx0 = sxx[rrow];
            float thr = t0 + 2.f * fmaf(2.5e-3f, sqrtf(xx0) * smax, 1e-2f);
            if (lane < 8) best64[wid * 8 + lane] = 0xFFFFFFFFFFFFFFFFull;
            __syncwarp();
#pragma unroll 1
            for (int c = (lane & 3); c < NCHUNK; c += 4) {
                float m10 = cmin[rrow * CMIN_STRIDE + c];
                uint32_t a0 = caux[rrow * CMIN_STRIDE + c];
                bool f0 = m10 <= thr;
                float m20 = __half2float(__ushort_as_half((unsigned short)(a0 >> 16)));
                bool ch0 = f0 && (m20 <= thr);
                unsigned bt0 = __ballot_sync(0xffffffffu, f0);
                int tot = __popc(bt0);
                int bs = 0;
                if (lane == 0 && tot) bs = atomicAdd(qn, tot);
                bs = __shfl_sync(0xffffffffu, bs, 0);
                unsigned lt = (1u << lane) - 1u;
                if (f0) {
                    int s_ = bs + __popc(bt0 & lt);
                    queue[s_] = ch0 ? (0x80000000u | ((uint32_t)rrow << 5) | (uint32_t)c)
                                    : (((uint32_t)rrow << 16) | (a0 & 0xffffu));
                }
            }
        }
        __syncthreads();  // queue complete

        const int nent = *qn;

        // ---- pass A: chunk entries (warps 0-7 have stage buffers) ----
        if (wid < 8) {
            float4* stg = (float4*)(smem + OFF_STAGE + wid * STG_STRIDE);
#pragma unroll 1
            for (int e = wid; e < nent; e += 8) {
                uint32_t ent = queue[e];
                if (!(ent & 0x80000000u)) continue;
                int row = (int)((ent >> 5) & 0x7f);
                int c = (int)(ent & 31);
                const float4* src = (const float4*)(emb + (c << 10));
#pragma unroll
                for (int j = 0; j < 8; j++) {
                    float4 v = __ldg(src + j * 32 + lane);
                    int jj = j * 32 + lane;
                    stg[(jj >> 4) * 17 + (jj & 15)] = v;
                }
                __syncwarp();
                u64 key = 0xFFFFFFFFFFFFFFFFull;
                if (lane < 16) {
                    const float4* xs = (const float4*)(smem + OFF_X + row * XSTRIDE);
                    const float4* ep = stg + lane * 17;
                    float s0 = 0.f, s1 = 0.f, s2 = 0.f, s3 = 0.f;
#pragma unroll
                    for (int q = 0; q < 16; q++) {
                        float4 e4 = ep[q];
                        float4 x4 = xs[q];
                        s0 = fmaf(x4.x, e4.x, s0);
                        s1 = fmaf(x4.y, e4.y, s1);
                        s2 = fmaf(x4.z, e4.z, s2);
                        s3 = fmaf(x4.w, e4.w, s3);
                    }
                    float d = (s0 + s1) + (s2 + s3);
                    int k = (c << 4) + lane;
                    float4 ew = eew[k];
                    float t = (sxx[row] + ew.x - 2.0f * d) * ew.y;
                    key = ((u64)__float_as_uint(t) << 32) | (unsigned)k;
                }
#pragma unroll
                for (int off = 16; off > 0; off >>= 1) {
                    u64 o = __shfl_xor_sync(0xffffffffu, key, off);
                    if (o < key) key = o;
                }
                if (lane == 0) atomicMin(&best64[row], key);
                __syncwarp();
            }
        }

        // ---- pass B: code entries, per-thread exact rescore ----
        for (int i = tid; i < nent; i += TPB) {
            uint32_t ent = queue[i];
            if (ent & 0x80000000u) continue;
            int row = (int)(ent >> 16);
            int k = (int)(ent & 0x1ff);
            const float4* ep = (const float4*)(emb + k * DIM);
            const float4* xs = (const float4*)(smem + OFF_X + row * XSTRIDE);
            float s0 = 0.f, s1 = 0.f, s2 = 0.f, s3 = 0.f;
#pragma unroll
            for (int q = 0; q < 16; q++) {
                float4 e4 = __ldg(ep + q);
                float4 x4 = xs[q];
                s0 = fmaf(x4.x, e4.x, s0);
                s1 = fmaf(x4.y, e4.y, s1);
                s2 = fmaf(x4.z, e4.z, s2);
                s3 = fmaf(x4.w, e4.w, s3);
            }
            float d = (s0 + s1) + (s2 + s3);
            float4 ew = eew[k];
            float t = (sxx[row] + ew.x - 2.0f * d) * ew.y;
            u64 key = ((u64)__float_as_uint(t) << 32) | (unsigned)k;
            atomicMin(&best64[row], key);
        }
        __syncthreads();  // best ready

        // ---- outputs: coalesced cooperative write + loss ----
        for (int idx = tid; idx < TILE_M * 16; idx += TPB) {
            int row = idx >> 4, q = idx & 15;
            int bk = (int)(best64[row] & 0x1ff);
            float4 e4 = __ldg((const float4*)(emb + bk * DIM) + q);
            float4 x4 = *(const float4*)(smem + OFF_X + row * XSTRIDE + q * 16);
            float dx = x4.x - e4.x, dy = x4.y - e4.y;
            float dz = x4.z - e4.z, dw = x4.w - e4.w;
            lsum += dx * dx + dy * dy + dz * dz + dw * dw;
            *((float4*)(out_q + (base + row) * DIM) + q) = e4;
            if (q == 0) out_idx[base + row] = (float)bk;
        }
    }

    // ---- loss block reduction ----
    __syncthreads();
    float* red = (float*)(smem + OFF_RED);
    red[tid] = lsum;
    __syncthreads();
#pragma unroll
    for (int s = TPB / 2; s > 0; s >>= 1) {
        if (tid < s) red[tid] += red[tid + s];
        __syncthreads();
    }

    // ---- last-CTA finalize (deterministic ordered sum) ----
    __shared__ unsigned int s_ticket;
    if (tid == 0) {
        atomicExch(&g_part[blockIdx.x], red[0]);
        __threadfence();
        s_ticket = atomicAdd(&g_ticket, 1u);
    }
    __syncthreads();
    if ((s_ticket % gridDim.x) == gridDim.x - 1) {
        __threadfence();
        if (tid < (int)gridDim.x) red[tid] = atomicAdd(&g_part[tid], 0.0f);
        __syncthreads();
        if (tid == 0) {
            float s = 0.f;
            for (int i = 0; i < (int)gridDim.x; i++) s += red[i];
            out_loss[0] = 0.25f * s * inv_count;
        }
    }
}

extern "C" void kernel_launch(void* const* d_in, const int* in_sizes, int n_in,
                              void* d_out, int out_size) {
    const float* inputs = (const float*)d_in[0];
    const float* emb    = (const float*)d_in[1];
    const float* ema    = (const float*)d_in[2];

    int N = in_sizes[0] / DIM;
    int ntiles = N / TILE_M;
    float* out = (float*)d_out;
    float* out_q    = out;
    float* out_loss = out + (size_t)N * DIM;
    float* out_idx  = out + (size_t)N * DIM + 1;

    static int grid = 0;
    if (grid == 0) {
        int sms = 0;
        cudaDeviceGetAttribute(&sms, cudaDevAttrMultiProcessorCount, 0);
        grid = (sms > 0 && sms <= MAXGRID) ? sms : 148;
        cudaFuncSetAttribute(vq_hmma, cudaFuncAttributeMaxDynamicSharedMemorySize,
                             SMEM_TOTAL);
    }

    vq_hmma<<<grid, TPB, SMEM_TOTAL>>>(inputs, emb, ema, out_q, out_idx,
                                       out_loss, ntiles,
                                       1.0f / ((float)N * (float)DIM));
}

// round 17
// speedup vs baseline: 1.4130x; 1.0582x over previous
#include <cuda_runtime.h>
#include <cuda_fp16.h>
#include <math.h>
#include <stdint.h>

// VectorQuantizerEMA: D=64, K=512, N=B*T=262144.
// fp16 HMMA screen, warp-owns-codes (2 chunks/warp, B frags in registers),
// TPB=512. R16 + coalesced A-build (fixes 2048 wf/tile scattered x LDG and
// 8-way-conflicted fp16-plane STS). All compared arithmetic bit-identical.
#define DIM 64
#define NCODES 512
#define TILE_M 128
#define TPB 512
#define NWARP 16
#define MAXGRID 256
#define NCHUNK 32
#define CMIN_STRIDE 33
#define QCAP 4096
#define XSTRIDE 272
#define STG_STRIDE 4352

__device__ float g_part[MAXGRID];
__device__ unsigned int g_ticket;

// ---------- smem layout (bytes) ----------
#define OFF_AH     0                   // A fp16 [128 x 128B] SW128      (16384)
#define OFF_BH     16384               // B fp16 [512 x 128B] SW128      (65536)
#define OFF_X      81920               // x fp32 [128 x 272B]            (34816)
#define OFF_EEW    116736              // float4[512]: (ee, w, s, 0)     (8192)
#define OFF_SEW    124928              // float2[512]: (w, ee*w)         (4096)
#define OFF_CMIN   129024              // f32[128][33] chunk min         (16896)
#define OFF_CAUX   145920              // u32[128][33] fp16(m2)<<16|k1   (16896)
#define OFF_SXX    162816              // f32[128]                       (512)
#define OFF_BEST   163328              // u64[128]                       (1024)
#define OFF_QUEUE  164352              // u32[QCAP]                      (16384)
#define OFF_CNT    180736              // qn @+0, smax @+8               (16)
#define OFF_STAGE  180752              // 8 stage buffers x 4352B        (34816)
#define OFF_RED    215568              // float[512]                     (2048)
#define SMEM_TOTAL 217616

#define SWZ(o) ((uint32_t)(o) ^ ((((uint32_t)(o)) >> 3) & 0x70))

typedef unsigned long long u64;

__device__ __forceinline__ uint32_t smem_u32(const void* p) {
    uint32_t a;
    asm("{ .reg .u64 t; cvta.to.shared.u64 t, %1; cvt.u32.u64 %0, t; }"
        : "=r"(a) : "l"(p));
    return a;
}
__device__ __forceinline__ void ldm4(uint32_t* r, uint32_t addr) {
    asm volatile("ldmatrix.sync.aligned.m8n8.x4.shared.b16 {%0,%1,%2,%3}, [%4];"
                 : "=r"(r[0]), "=r"(r[1]), "=r"(r[2]), "=r"(r[3]) : "r"(addr));
}
__device__ __forceinline__ void mma16816(float* c, const uint32_t* a,
                                         const uint32_t* b) {
    asm volatile(
        "mma.sync.aligned.m16n8k16.row.col.f32.f16.f16.f32 "
        "{%0,%1,%2,%3}, {%4,%5,%6,%7}, {%8,%9}, {%0,%1,%2,%3};"
        : "+f"(c[0]), "+f"(c[1]), "+f"(c[2]), "+f"(c[3])
        : "r"(a[0]), "r"(a[1]), "r"(a[2]), "r"(a[3]), "r"(b[0]), "r"(b[1]));
}
__device__ __forceinline__ uint32_t packh2(float a, float b) {
    __half2 h = __floats2half2_rn(a, b);
    return *(uint32_t*)&h;
}

__global__ void __launch_bounds__(TPB, 1)
vq_hmma(const float* __restrict__ inputs,
        const float* __restrict__ emb,
        const float* __restrict__ ema,
        float* __restrict__ out_q,
        float* __restrict__ out_idx,
        float* __restrict__ out_loss,
        int ntiles, float inv_count) {
    extern __shared__ char smem[];
    const uint32_t sbase = smem_u32(smem);
    const int tid  = threadIdx.x;
    const int wid  = tid >> 5;
    const int lane = tid & 31;

    float4* eew   = (float4*)(smem + OFF_EEW);
    float2* sew   = (float2*)(smem + OFF_SEW);
    float*  cmin  = (float*)(smem + OFF_CMIN);
    uint32_t* caux = (uint32_t*)(smem + OFF_CAUX);
    float*  sxx   = (float*)(smem + OFF_SXX);
    u64*    best64 = (u64*)(smem + OFF_BEST);
    uint32_t* queue = (uint32_t*)(smem + OFF_QUEUE);
    int* qn = (int*)(smem + OFF_CNT);

    if (tid == 0) *(int*)(smem + OFF_CNT + 8) = 0;
    __syncthreads();

    // ---- codebook init: fp16 plane + (ee, w, s) + (w, ee*w) ----
    for (int k = tid; k < NCODES; k += TPB) {
        const float* e = emb + k * DIM;
        float ee = 0.f;
#pragma unroll
        for (int d = 0; d < DIM; d++) ee += e[d] * e[d];
        const float4* ep = (const float4*)e;
#pragma unroll
        for (int q = 0; q < 16; q++) {
            float4 e4 = ep[q];
            uint2 hv = make_uint2(packh2(e4.x, e4.y), packh2(e4.z, e4.w));
            *(uint2*)(smem + OFF_BH + SWZ(k * 128 + q * 8)) = hv;
        }
        float w = sqrtf(ema[k]);
        float s = sqrtf(ee) * w;
        eew[k] = make_float4(ee, w, s, 0.f);
        sew[k] = make_float2(w, ee * w);
        atomicMax((int*)(smem + OFF_CNT + 8), __float_as_int(s));  // s >= 0
    }
    __syncthreads();
    const float smax = *(float*)(smem + OFF_CNT + 8);

    // fragment geometry
    const int rowAoff = ((lane >> 3) & 1) * 8 + (lane & 7);   // within row-group
    const uint32_t kaddA = ((lane >> 4) & 1) * 16;
    const int rowB = ((lane >> 4) & 1) * 8 + (lane & 7);
    const uint32_t kaddB = ((lane >> 3) & 1) * 16;
    const int rsub = lane >> 2;          // epilogue row within group (0..7)
    const int jcol = (lane & 3) * 2;     // epilogue col pair within chunk

    // ---- B fragments: this warp's 2 chunks, ALL tiles, in registers ----
    uint32_t bf[2][4][4];
#pragma unroll
    for (int i = 0; i < 2; i++) {
        const int nb = (wid * 2 + i) * 16;
#pragma unroll
        for (int s = 0; s < 4; s++)
            ldm4(bf[i][s], sbase + OFF_BH + SWZ((nb + rowB) * 128 + s * 32 + kaddB));
    }

    float lsum = 0.f;

    for (int tile = blockIdx.x; tile < ntiles; tile += gridDim.x) {
        const size_t base = (size_t)tile * TILE_M;
        __syncthreads();  // prev tile fully consumed

        // ---- A-build phase 1: COALESCED copy + fp16 plane ----
        // flat i = row*16 + q; consecutive threads -> consecutive gmem float4s
        {
            const float4* src = (const float4*)(inputs + base * DIM);
#pragma unroll
            for (int i = tid; i < TILE_M * 16; i += TPB) {
                int row = i >> 4, q = i & 15;
                float4 v = __ldg(src + i);
                *(float4*)(smem + OFF_X + row * XSTRIDE + q * 16) = v;
                uint2 hv = make_uint2(packh2(v.x, v.y), packh2(v.z, v.w));
                *(uint2*)(smem + OFF_AH + SWZ(row * 128 + q * 8)) = hv;
            }
        }
        if (tid == 0) *qn = 0;
        __syncthreads();  // X complete

        // ---- A-build phase 2: xx with bit-identical serial arithmetic ----
        if (tid < TILE_M) {
            const float4* xs = (const float4*)(smem + OFF_X + tid * XSTRIDE);
            float xxr = 0.f;
#pragma unroll
            for (int q = 0; q < 16; q++) {
                float4 v = xs[q];
                xxr += v.x * v.x + v.y * v.y + v.z * v.z + v.w * v.w;
            }
            sxx[tid] = xxr;
        }
        __syncthreads();  // A + sxx ready

        // ---- screen: 8 row-groups x (this warp's 2 chunks) ----
#pragma unroll 1
        for (int rg = 0; rg < 8; rg++) {
            const int rbase = rg * 16;
            uint32_t ah[4][4];
#pragma unroll
            for (int s = 0; s < 4; s++)
                ldm4(ah[s], sbase + OFF_AH +
                            SWZ((rbase + rowAoff) * 128 + s * 32 + kaddA));

            const int rrow0 = rbase + rsub;
            const int rrow1 = rrow0 + 8;
            const float xx0 = sxx[rrow0];
            const float xx1 = sxx[rrow1];

#pragma unroll
            for (int i = 0; i < 2; i++) {
                const int cc = wid * 2 + i;
                const int nb = cc * 16;
                float acc0[4] = {0.f, 0.f, 0.f, 0.f};
                float acc1[4] = {0.f, 0.f, 0.f, 0.f};
#pragma unroll
                for (int s = 0; s < 4; s++) {
                    mma16816(acc0, ah[s], bf[i][s] + 0);
                    mma16816(acc1, ah[s], bf[i][s] + 2);
                }
                const int c0 = nb + jcol;
                const int c2 = nb + jcol + 8;
                float2 s00 = sew[c0];
                float2 s01 = sew[c0 + 1];
                float2 s10 = sew[c2];
                float2 s11 = sew[c2 + 1];
                float w2a = -(s00.x + s00.x);
                float w2b = -(s01.x + s01.x);
                float w2c = -(s10.x + s10.x);
                float w2d = -(s11.x + s11.x);
                float d00 = fmaf(acc0[0], w2a, fmaf(xx0, s00.x, s00.y));
                float d01 = fmaf(acc0[1], w2b, fmaf(xx0, s01.x, s01.y));
                float d02 = fmaf(acc1[0], w2c, fmaf(xx0, s10.x, s10.y));
                float d03 = fmaf(acc1[1], w2d, fmaf(xx0, s11.x, s11.y));
                float d10 = fmaf(acc0[2], w2a, fmaf(xx1, s00.x, s00.y));
                float d11 = fmaf(acc0[3], w2b, fmaf(xx1, s01.x, s01.y));
                float d12 = fmaf(acc1[2], w2c, fmaf(xx1, s10.x, s10.y));
                float d13 = fmaf(acc1[3], w2d, fmaf(xx1, s11.x, s11.y));

                // lane-local top-2 (value, code) for each row
                float m1 = d00; int k1 = c0; float m2 = d01;
                if (d01 < m1) { m2 = m1; m1 = d01; k1 = c0 + 1; }
                if (d02 < m1) { m2 = m1; m1 = d02; k1 = c2; } else m2 = fminf(m2, d02);
                if (d03 < m1) { m2 = m1; m1 = d03; k1 = c2 + 1; } else m2 = fminf(m2, d03);
                float p1 = d10; int l1 = c0; float p2 = d11;
                if (d11 < p1) { p2 = p1; p1 = d11; l1 = c0 + 1; }
                if (d12 < p1) { p2 = p1; p1 = d12; l1 = c2; } else p2 = fminf(p2, d12);
                if (d13 < p1) { p2 = p1; p1 = d13; l1 = c2 + 1; } else p2 = fminf(p2, d13);

                // merge across the 4 lanes of the row-group
#pragma unroll
                for (int off = 1; off <= 2; off <<= 1) {
                    float om1 = __shfl_xor_sync(0xffffffffu, m1, off);
                    int   ok1 = __shfl_xor_sync(0xffffffffu, k1, off);
                    float om2 = __shfl_xor_sync(0xffffffffu, m2, off);
                    if (om1 < m1) { m2 = fminf(m1, om2); m1 = om1; k1 = ok1; }
                    else          { m2 = fminf(m2, om1); }
                    float op1 = __shfl_xor_sync(0xffffffffu, p1, off);
                    int   ol1 = __shfl_xor_sync(0xffffffffu, l1, off);
                    float op2 = __shfl_xor_sync(0xffffffffu, p2, off);
                    if (op1 < p1) { p2 = fminf(p1, op2); p1 = op1; l1 = ol1; }
                    else          { p2 = fminf(p2, op1); }
                }
                if ((lane & 3) == 0) {
                    cmin[rrow0 * CMIN_STRIDE + cc] = m1;
                    cmin[rrow1 * CMIN_STRIDE + cc] = p1;
                    caux[rrow0 * CMIN_STRIDE + cc] =
                        ((uint32_t)__half_as_ushort(__float2half_rd(m2)) << 16) |
                        (uint32_t)k1;
                    caux[rrow1 * CMIN_STRIDE + cc] =
                        ((uint32_t)__half_as_ushort(__float2half_rd(p2)) << 16) |
                        (uint32_t)l1;
                }
            }
        }
        __syncthreads();  // cmin/caux ready (cross-warp)

        // ---- phase 2a: 8 rows per warp; row mins + ballot enqueue ----
        {
            const int rrow = wid * 8 + rsub;    // 16 warps x 8 rows = 128
            float t0 = __int_as_float(0x7f800000);
#pragma unroll
            for (int c = (lane & 3); c < NCHUNK; c += 4)
                t0 = fminf(t0, cmin[rrow * CMIN_STRIDE + c]);
            t0 = fminf(t0, __shfl_xor_sync(0xffffffffu, t0, 1));
            t0 = fminf(t0, __shfl_xor_sync(0xffffffffu, t0, 2));
            const float xx0 = sxx[rrow];
            float thr = t0 + 2.f * fmaf(2.5e-3f, sqrtf(xx0) * smax, 1e-2f);
            if (lane < 8) best64[wid * 8 + lane] = 0xFFFFFFFFFFFFFFFFull;
            __syncwarp();
#pragma unroll 1
            for (int c = (lane & 3); c < NCHUNK; c += 4) {
                float m10 = cmin[rrow * CMIN_STRIDE + c];
                uint32_t a0 = caux[rrow * CMIN_STRIDE + c];
                bool f0 = m10 <= thr;
                float m20 = __half2float(__ushort_as_half((unsigned short)(a0 >> 16)));
                bool ch0 = f0 && (m20 <= thr);
                unsigned bt0 = __ballot_sync(0xffffffffu, f0);
                int tot = __popc(bt0);
                int bs = 0;
                if (lane == 0 && tot) bs = atomicAdd(qn, tot);
                bs = __shfl_sync(0xffffffffu, bs, 0);
                unsigned lt = (1u << lane) - 1u;
                if (f0) {
                    int s_ = bs + __popc(bt0 & lt);
                    queue[s_] = ch0 ? (0x80000000u | ((uint32_t)rrow << 5) | (uint32_t)c)
                                    : (((uint32_t)rrow << 16) | (a0 & 0xffffu));
                }
            }
        }
        __syncthreads();  // queue complete

        const int nent = *qn;

        // ---- pass A: chunk entries (warps 0-7 have stage buffers) ----
        if (wid < 8) {
            float4* stg = (float4*)(smem + OFF_STAGE + wid * STG_STRIDE);
#pragma unroll 1
            for (int e = wid; e < nent; e += 8) {
                uint32_t ent = queue[e];
                if (!(ent & 0x80000000u)) continue;
                int row = (int)((ent >> 5) & 0x7f);
                int c = (int)(ent & 31);
                const float4* src = (const float4*)(emb + (c << 10));
#pragma unroll
                for (int j = 0; j < 8; j++) {
                    float4 v = __ldg(src + j * 32 + lane);
                    int jj = j * 32 + lane;
                    stg[(jj >> 4) * 17 + (jj & 15)] = v;
                }
                __syncwarp();
                u64 key = 0xFFFFFFFFFFFFFFFFull;
                if (lane < 16) {
                    const float4* xs = (const float4*)(smem + OFF_X + row * XSTRIDE);
                    const float4* ep = stg + lane * 17;
                    float s0 = 0.f, s1 = 0.f, s2 = 0.f, s3 = 0.f;
#pragma unroll
                    for (int q = 0; q < 16; q++) {
                        float4 e4 = ep[q];
                        float4 x4 = xs[q];
                        s0 = fmaf(x4.x, e4.x, s0);
                        s1 = fmaf(x4.y, e4.y, s1);
                        s2 = fmaf(x4.z, e4.z, s2);
                        s3 = fmaf(x4.w, e4.w, s3);
                    }
                    float d = (s0 + s1) + (s2 + s3);
                    int k = (c << 4) + lane;
                    float4 ew = eew[k];
                    float t = (sxx[row] + ew.x - 2.0f * d) * ew.y;
                    key = ((u64)__float_as_uint(t) << 32) | (unsigned)k;
                }
#pragma unroll
                for (int off = 16; off > 0; off >>= 1) {
                    u64 o = __shfl_xor_sync(0xffffffffu, key, off);
                    if (o < key) key = o;
                }
                if (lane == 0) atomicMin(&best64[row], key);
                __syncwarp();
            }
        }

        // ---- pass B: code entries, per-thread exact rescore ----
        for (int i = tid; i < nent; i += TPB) {
            uint32_t ent = queue[i];
            if (ent & 0x80000000u) continue;
            int row = (int)(ent >> 16);
            int k = (int)(ent & 0x1ff);
            const float4* ep = (const float4*)(emb + k * DIM);
            const float4* xs = (const float4*)(smem + OFF_X + row * XSTRIDE);
            float s0 = 0.f, s1 = 0.f, s2 = 0.f, s3 = 0.f;
#pragma unroll
            for (int q = 0; q < 16; q++) {
                float4 e4 = __ldg(ep + q);
                float4 x4 = xs[q];
                s0 = fmaf(x4.x, e4.x, s0);
                s1 = fmaf(x4.y, e4.y, s1);
                s2 = fmaf(x4.z, e4.z, s2);
                s3 = fmaf(x4.w, e4.w, s3);
            }
            float d = (s0 + s1) + (s2 + s3);
            float4 ew = eew[k];
            float t = (sxx[row] + ew.x - 2.0f * d) * ew.y;
            u64 key = ((u64)__float_as_uint(t) << 32) | (unsigned)k;
            atomicMin(&best64[row], key);
        }
        __syncthreads();  // best ready

        // ---- outputs: coalesced cooperative write + loss ----
        for (int idx = tid; idx < TILE_M * 16; idx += TPB) {
            int row = idx >> 4, q = idx & 15;
            int bk = (int)(best64[row] & 0x1ff);
            float4 e4 = __ldg((const float4*)(emb + bk * DIM) + q);
            float4 x4 = *(const float4*)(smem + OFF_X + row * XSTRIDE + q * 16);
            float dx = x4.x - e4.x, dy = x4.y - e4.y;
            float dz = x4.z - e4.z, dw = x4.w - e4.w;
            lsum += dx * dx + dy * dy + dz * dz + dw * dw;
            *((float4*)(out_q + (base + row) * DIM) + q) = e4;
            if (q == 0) out_idx[base + row] = (float)bk;
        }
    }

    // ---- loss block reduction ----
    __syncthreads();
    float* red = (float*)(smem + OFF_RED);
    red[tid] = lsum;
    __syncthreads();
#pragma unroll
    for (int s = TPB / 2; s > 0; s >>= 1) {
        if (tid < s) red[tid] += red[tid + s];
        __syncthreads();
    }

    // ---- last-CTA finalize (deterministic ordered sum) ----
    __shared__ unsigned int s_ticket;
    if (tid == 0) {
        atomicExch(&g_part[blockIdx.x], red[0]);
        __threadfence();
        s_ticket = atomicAdd(&g_ticket, 1u);
    }
    __syncthreads();
    if ((s_ticket % gridDim.x) == gridDim.x - 1) {
        __threadfence();
        if (tid < (int)gridDim.x) red[tid] = atomicAdd(&g_part[tid], 0.0f);
        __syncthreads();
        if (tid == 0) {
            float s = 0.f;
            for (int i = 0; i < (int)gridDim.x; i++) s += red[i];
            out_loss[0] = 0.25f * s * inv_count;
        }
    }
}

extern "C" void kernel_launch(void* const* d_in, const int* in_sizes, int n_in,
                              void* d_out, int out_size) {
    const float* inputs = (const float*)d_in[0];
    const float* emb    = (const float*)d_in[1];
    const float* ema    = (const float*)d_in[2];

    int N = in_sizes[0] / DIM;
    int ntiles = N / TILE_M;
    float* out = (float*)d_out;
    float* out_q    = out;
    float* out_loss = out + (size_t)N * DIM;
    float* out_idx  = out + (size_t)N * DIM + 1;

    static int grid = 0;
    if (grid == 0) {
        int sms = 0;
        cudaDeviceGetAttribute(&sms, cudaDevAttrMultiProcessorCount, 0);
        grid = (sms > 0 && sms <= MAXGRID) ? sms : 148;
        cudaFuncSetAttribute(vq_hmma, cudaFuncAttributeMaxDynamicSharedMemorySize,
                             SMEM_TOTAL);
    }

    vq_hmma<<<grid, TPB, SMEM_TOTAL>>>(inputs, emb, ema, out_q, out_idx,
                                       out_loss, ntiles,
                                       1.0f / ((float)N * (float)DIM));
}